// round 6
// baseline (speedup 1.0000x reference)
#include <cuda_runtime.h>
#include <cuda_bf16.h>
#include <math.h>
#include <stdint.h>

// ---------------- problem constants ----------------
// B=16, Cmel=80, Ctxt=256, Catt=80, T1=800, T2=200
#define NB   16
#define T1D  800
#define T2D  200

// ---------------- scratch (no allocation allowed) ----------------
__device__ __nv_bfloat16 g_k1b[16 * 512 * 200];  // key conv1 output (relu)
__device__ __nv_bfloat16 g_kkb[16 * 80 * 200];   // key encoder output k
__device__ __nv_bfloat16 g_q1b[16 * 160 * 800];  // query conv1 output (relu)
__device__ __nv_bfloat16 g_qmb[16 * 80 * 800];   // query conv2 output (relu)
__device__ __nv_bfloat16 g_qqb[16 * 80 * 800];   // query encoder output q
__device__ float g_k2[16 * 200];                 // ||k||^2 per (b,t2)
__device__ float g_q2[16 * 800];                 // ||q||^2 per (b,t1)

// ---------------- helpers ----------------
__device__ __forceinline__ uint32_t smem_u32(const void* p) {
    uint32_t a;
    asm("{ .reg .u64 t; cvta.to.shared.u64 t, %1; cvt.u32.u64 %0, t; }" : "=r"(a) : "l"(p));
    return a;
}
__device__ __forceinline__ float tofloat(float v) { return v; }
__device__ __forceinline__ float tofloat(__nv_bfloat16 v) { return __bfloat162float(v); }

__device__ __forceinline__ void ldsm_x4(uint32_t& r0, uint32_t& r1, uint32_t& r2, uint32_t& r3,
                                        uint32_t addr) {
    asm volatile("ldmatrix.sync.aligned.m8n8.x4.shared.b16 {%0,%1,%2,%3}, [%4];"
                 : "=r"(r0), "=r"(r1), "=r"(r2), "=r"(r3) : "r"(addr));
}
__device__ __forceinline__ void ldsm_x2(uint32_t& r0, uint32_t& r1, uint32_t addr) {
    asm volatile("ldmatrix.sync.aligned.m8n8.x2.shared.b16 {%0,%1}, [%2];"
                 : "=r"(r0), "=r"(r1) : "r"(addr));
}
__device__ __forceinline__ void mma16816(float* c, uint32_t a0, uint32_t a1, uint32_t a2,
                                         uint32_t a3, uint32_t b0, uint32_t b1) {
    asm volatile("mma.sync.aligned.m16n8k16.row.col.f32.bf16.bf16.f32 "
                 "{%0,%1,%2,%3}, {%4,%5,%6,%7}, {%8,%9}, {%0,%1,%2,%3};"
                 : "+f"(c[0]), "+f"(c[1]), "+f"(c[2]), "+f"(c[3])
                 : "r"(a0), "r"(a1), "r"(a2), "r"(a3), "r"(b0), "r"(b1));
}

// ---------------- generic conv-as-GEMM via bf16 mma.sync ----------------
// Y[b, co, t] = sum_s sum_ci W[co, ci, s] * X[b, ci, t + s - PAD] + bias  (opt ReLU)
// Block: WM x WN warps. Warp (wm, wn) computes m16 rows at co0+wm*16,
// NT n-tiles of 8 t each at t0 + wn*NT*8. X staged t-major [t][ci16] (stride 24)
// so tap shifts change the ldmatrix row only. Canonical m16n8k16 frags.
template<typename TIN, int KT, int CIN, int WM, int WN, int NT, bool RELU>
__global__ __launch_bounds__(32 * WM * WN)
void conv_mma_kernel(const TIN* __restrict__ x, const float* __restrict__ w,
                     const float* __restrict__ bias, __nv_bfloat16* __restrict__ y,
                     int Cout, int T)
{
    constexpr int THREADS = 32 * WM * WN;
    constexpr int BM  = 16 * WM;
    constexpr int BN  = 8 * NT * WN;
    constexpr int PAD = (KT == 3) ? 1 : 0;
    constexpr int BNH = BN + 2 * PAD;
    constexpr int XS  = 24;          // xs row stride (bf16 elems): 48B, 16B-aligned rows
    constexpr int NCH = CIN / 16;

    __shared__ __nv_bfloat16 xs[BNH * XS];
    __shared__ __nv_bfloat16 ws[KT * BM * 16];

    const int b    = blockIdx.z;
    const int co0  = blockIdx.y * BM;
    const int t0   = blockIdx.x * BN;
    const int tid  = threadIdx.x;
    const int lane = tid & 31;
    const int warp = tid >> 5;
    const int wm   = warp % WM;
    const int wn   = warp / WM;

    float acc[NT][4];
    #pragma unroll
    for (int nt = 0; nt < NT; ++nt)
        #pragma unroll
        for (int i = 0; i < 4; ++i) acc[nt][i] = 0.f;

    const uint32_t xs_u = smem_u32(xs);
    const uint32_t ws_u = smem_u32(ws);

    // ldmatrix per-lane address components (canonical m16n8k16 tiles)
    const int a_row = lane & 15;               // A: lanes 0-15 rows, 16-31 k-half 8
    const int a_kh  = (lane >> 4) * 8;
    const int b_row = (lane & 7) + ((lane >> 4) & 1) * 8;  // B x4: 2 n-tiles
    const int b_kh  = ((lane >> 3) & 1) * 8;
    const int b_row2 = lane & 7;               // B x2: lanes 0-15 only

    const TIN* xb = x + (size_t)b * CIN * T;

    for (int cc = 0; cc < NCH; ++cc) {
        __syncthreads();
        // stage X chunk: rows r = t0 + r - PAD, cols ci (16). Coalesced over r.
        for (int idx = tid; idx < BNH * 16; idx += THREADS) {
            int r = idx % BNH, ci = idx / BNH;
            int t = t0 + r - PAD;
            float v = 0.f;
            if (t >= 0 && t < T) v = tofloat(xb[(size_t)(cc * 16 + ci) * T + t]);
            xs[r * XS + ci] = __float2bfloat16(v);
        }
        // stage W chunk: [s][co][k16]. W gmem layout (Cout, Cin, KT).
        for (int idx = tid; idx < BM * 16 * KT; idx += THREADS) {
            int co = idx / (16 * KT);
            int rem = idx % (16 * KT);
            int k = rem / KT, s = rem % KT;
            float v = w[(size_t)(co0 + co) * (CIN * KT) + (size_t)(cc * 16 + k) * KT + s];
            ws[(s * BM + co) * 16 + k] = __float2bfloat16(v);
        }
        __syncthreads();

        #pragma unroll
        for (int s = 0; s < KT; ++s) {
            uint32_t a0, a1, a2, a3;
            uint32_t aaddr = ws_u + (uint32_t)(((s * BM + wm * 16 + a_row) * 16 + a_kh) * 2);
            ldsm_x4(a0, a1, a2, a3, aaddr);
            const int ss = (KT == 3) ? s : 0;
            #pragma unroll
            for (int nt = 0; nt + 1 < NT; nt += 2) {
                int n_base = wn * NT * 8 + nt * 8;
                uint32_t baddr = xs_u + (uint32_t)((((n_base + b_row + ss) * XS) + b_kh) * 2);
                uint32_t b0, b1, b2, b3;
                ldsm_x4(b0, b1, b2, b3, baddr);
                mma16816(acc[nt],     a0, a1, a2, a3, b0, b1);
                mma16816(acc[nt + 1], a0, a1, a2, a3, b2, b3);
            }
            if (NT & 1) {
                int nt = NT - 1;
                int n_base = wn * NT * 8 + nt * 8;
                uint32_t baddr = xs_u + (uint32_t)((((n_base + b_row2 + ss) * XS) + b_kh) * 2);
                uint32_t b0, b1;
                ldsm_x2(b0, b1, baddr);
                mma16816(acc[nt], a0, a1, a2, a3, b0, b1);
            }
        }
    }

    // epilogue: c0,c1 -> (row g, t tg*2,+1); c2,c3 -> row g+8. t even, T even -> pair stores ok.
    const int g = lane >> 2, tg = lane & 3;
    const int coA = co0 + wm * 16 + g;
    const int coB = coA + 8;
    const float bA = bias[coA], bB = bias[coB];
    __nv_bfloat16* yb = y + (size_t)b * Cout * T;
    #pragma unroll
    for (int nt = 0; nt < NT; ++nt) {
        int t = t0 + wn * NT * 8 + nt * 8 + tg * 2;
        if (t < T) {
            float v0 = acc[nt][0] + bA, v1 = acc[nt][1] + bA;
            float v2 = acc[nt][2] + bB, v3 = acc[nt][3] + bB;
            if (RELU) {
                v0 = v0 > 0.f ? v0 : 0.f; v1 = v1 > 0.f ? v1 : 0.f;
                v2 = v2 > 0.f ? v2 : 0.f; v3 = v3 > 0.f ? v3 : 0.f;
            }
            __nv_bfloat162 p0, p1;
            p0.x = __float2bfloat16(v0); p0.y = __float2bfloat16(v1);
            p1.x = __float2bfloat16(v2); p1.y = __float2bfloat16(v3);
            *(__nv_bfloat162*)(yb + (size_t)coA * T + t) = p0;
            *(__nv_bfloat162*)(yb + (size_t)coB * T + t) = p1;
        }
    }
}

// ---------------- sum of squares over channels (bf16 input) ----------------
__global__ void sumsq_bf_kernel(const __nv_bfloat16* __restrict__ x, float* __restrict__ out,
                                int C, int T, int total)
{
    int idx = blockIdx.x * blockDim.x + threadIdx.x;
    if (idx >= total) return;
    int b = idx / T, t = idx % T;
    const __nv_bfloat16* p = x + (size_t)b * C * T + t;
    float s = 0.f;
    for (int c = 0; c < C; ++c) {
        float v = __bfloat162float(p[(size_t)c * T]);
        s = fmaf(v, v, s);
    }
    out[idx] = s;
}

// ---------------- logits = -5e-4 * (||q||^2 + ||k||^2 - 2 q.k) ----------------
// grid (25, 16): block covers 32 t1 x 200 t2. 128 threads: thread = 2 t1 x 25 t2.
__global__ __launch_bounds__(128)
void attn_logits_kernel(const __nv_bfloat16* __restrict__ q, const __nv_bfloat16* __restrict__ k,
                        const float* __restrict__ q2, const float* __restrict__ k2,
                        float* __restrict__ out)
{
    constexpr int C = 80;
    __shared__ float ks[40 * T2D];
    __shared__ float qs[32 * 81];
    __shared__ float k2s[T2D];

    const int b      = blockIdx.y;
    const int t1base = blockIdx.x * 32;
    const int tid    = threadIdx.x;
    const int t1l    = tid >> 3;       // 0..15
    const int t2g    = tid & 7;
    const int toff   = t2g * 25;

    float acc0[25], acc1[25];
    #pragma unroll
    for (int j = 0; j < 25; ++j) { acc0[j] = 0.f; acc1[j] = 0.f; }

    for (int idx = tid; idx < 32 * C; idx += 128) {
        int c = idx >> 5, r = idx & 31;   // coalesced over r
        qs[r * 81 + c] = __bfloat162float(q[((size_t)b * C + c) * T1D + t1base + r]);
    }
    for (int idx = tid; idx < T2D; idx += 128) k2s[idx] = k2[b * T2D + idx];
    float q2v0 = q2[b * T1D + t1base + t1l];
    float q2v1 = q2[b * T1D + t1base + t1l + 16];

    for (int cc = 0; cc < 2; ++cc) {
        for (int idx = tid; idx < 40 * T2D; idx += 128) {
            ks[idx] = __bfloat162float(
                k[((size_t)b * C + cc * 40 + (idx / T2D)) * T2D + (idx % T2D)]);
        }
        __syncthreads();
        for (int ci = 0; ci < 40; ++ci) {
            float qv0 = qs[t1l * 81 + cc * 40 + ci];
            float qv1 = qs[(t1l + 16) * 81 + cc * 40 + ci];
            const float* kr = &ks[ci * T2D + toff];
            #pragma unroll
            for (int j = 0; j < 25; ++j) {
                float kv = kr[j];
                acc0[j] = fmaf(qv0, kv, acc0[j]);
                acc1[j] = fmaf(qv1, kv, acc1[j]);
            }
        }
        __syncthreads();
    }

    const int t1a = t1base + t1l;
    float* o0 = out + ((size_t)b * T1D + t1a) * T2D + toff;
    float* o1 = out + ((size_t)b * T1D + t1a + 16) * T2D + toff;
    #pragma unroll
    for (int j = 0; j < 25; ++j) {
        float kk = k2s[toff + j];
        o0[j] = -0.0005f * (q2v0 + kk - 2.f * acc0[j]);
        o1[j] = -0.0005f * (q2v1 + kk - 2.f * acc1[j]);
    }
}

// ---------------- in-place log_softmax over t2 + log(prior + 1e-8) ----------------
// one warp per (b,t1) row of 200.
__global__ __launch_bounds__(256)
void softmax_prior_kernel(float* __restrict__ out, const float* __restrict__ prior)
{
    int row  = blockIdx.x * 8 + (threadIdx.x >> 5);
    int lane = threadIdx.x & 31;
    float* p = out + (size_t)row * T2D;
    const float* pr = prior + (size_t)row * T2D;

    float v[7];
    float m = -1e30f;
    #pragma unroll
    for (int kk = 0; kk < 7; ++kk) {
        int i = lane + kk * 32;
        v[kk] = (i < T2D) ? p[i] : -1e30f;
        m = fmaxf(m, v[kk]);
    }
    #pragma unroll
    for (int off = 16; off; off >>= 1) m = fmaxf(m, __shfl_xor_sync(0xffffffff, m, off));
    float s = 0.f;
    #pragma unroll
    for (int kk = 0; kk < 7; ++kk) s += expf(v[kk] - m);
    #pragma unroll
    for (int off = 16; off; off >>= 1) s += __shfl_xor_sync(0xffffffff, s, off);
    float L = m + logf(s);
    #pragma unroll
    for (int kk = 0; kk < 7; ++kk) {
        int i = lane + kk * 32;
        if (i < T2D) p[i] = v[kk] - L + logf(pr[i] + 1e-8f);
    }
}

// ---------------- launch ----------------
extern "C" void kernel_launch(void* const* d_in, const int* in_sizes, int n_in,
                              void* d_out, int out_size)
{
    const float* queries = (const float*)d_in[0];   // (16,80,800)
    const float* keys    = (const float*)d_in[1];   // (16,256,200)
    const float* prior   = (const float*)d_in[2];   // (16,800,200)
    const float* kw1     = (const float*)d_in[3];   // (512,256,3)
    const float* kb1     = (const float*)d_in[4];
    const float* kw2     = (const float*)d_in[5];   // (80,512,1)
    const float* kb2     = (const float*)d_in[6];
    const float* qw1     = (const float*)d_in[7];   // (160,80,3)
    const float* qb1     = (const float*)d_in[8];
    const float* qw2     = (const float*)d_in[9];   // (80,160,1)
    const float* qb2     = (const float*)d_in[10];
    const float* qw3     = (const float*)d_in[11];  // (80,80,1)
    const float* qb3     = (const float*)d_in[12];
    float* out = (float*)d_out;

    __nv_bfloat16 *k1b, *kkb, *q1b, *qmb, *qqb;
    float *k2p, *q2p;
    cudaGetSymbolAddress((void**)&k1b, g_k1b);
    cudaGetSymbolAddress((void**)&kkb, g_kkb);
    cudaGetSymbolAddress((void**)&q1b, g_q1b);
    cudaGetSymbolAddress((void**)&qmb, g_qmb);
    cudaGetSymbolAddress((void**)&qqb, g_qqb);
    cudaGetSymbolAddress((void**)&k2p, g_k2);
    cudaGetSymbolAddress((void**)&q2p, g_q2);

    // key encoder: 256->512 k3 relu; 512->80 1x1
    // BM=32, BN=208 (2x2 warps, NT=13): grid (1, 512/32=16, 16)
    conv_mma_kernel<float, 3, 256, 2, 2, 13, true>
        <<<dim3(1, 16, NB), 128>>>(keys, kw1, kb1, k1b, 512, T2D);
    // BM=16, BN=224 (1x4 warps, NT=7): grid (1, 80/16=5, 16)
    conv_mma_kernel<__nv_bfloat16, 1, 512, 1, 4, 7, false>
        <<<dim3(1, 5, NB), 128>>>(k1b, kw2, kb2, kkb, 80, T2D);
    sumsq_bf_kernel<<<(NB * T2D + 255) / 256, 256>>>(kkb, k2p, 80, T2D, NB * T2D);

    // query encoder: 80->160 k3 relu; 160->80 1x1 relu; 80->80 1x1
    conv_mma_kernel<float, 3, 80, 2, 2, 13, true>
        <<<dim3(4, 5, NB), 128>>>(queries, qw1, qb1, q1b, 160, T1D);
    conv_mma_kernel<__nv_bfloat16, 1, 160, 1, 4, 7, true>
        <<<dim3(4, 5, NB), 128>>>(q1b, qw2, qb2, qmb, 80, T1D);
    conv_mma_kernel<__nv_bfloat16, 1, 80, 1, 4, 7, false>
        <<<dim3(4, 5, NB), 128>>>(qmb, qw3, qb3, qqb, 80, T1D);
    sumsq_bf_kernel<<<(NB * T1D + 255) / 256, 256>>>(qqb, q2p, 80, T1D, NB * T1D);

    // attention logits + log_softmax + prior
    attn_logits_kernel<<<dim3(25, NB), 128>>>(qqb, kkb, q2p, k2p, out);
    softmax_prior_kernel<<<NB * T1D / 8, 256>>>(out, prior);
}

// round 9
// speedup vs baseline: 2.5579x; 2.5579x over previous
#include <cuda_runtime.h>
#include <cuda_bf16.h>
#include <math.h>
#include <stdint.h>

// ---------------- problem constants ----------------
// B=16, Cmel=80, Ctxt=256, Catt=80, T1=800, T2=200
#define NB   16
#define T1D  800
#define T2D  200

// ---------------- scratch (no allocation allowed) ----------------
__device__ __nv_bfloat16 g_k1b[16 * 512 * 200];  // key conv1 output (relu)
__device__ __nv_bfloat16 g_kkb[16 * 80 * 200];   // key encoder output k
__device__ __nv_bfloat16 g_q1b[16 * 160 * 800];  // query conv1 output (relu)
__device__ __nv_bfloat16 g_qmb[16 * 80 * 800];   // query conv2 output (relu)
__device__ __nv_bfloat16 g_qqb[16 * 80 * 800];   // query encoder output q
__device__ float g_k2[16 * 200];                 // ||k||^2 per (b,t2)
__device__ float g_q2[16 * 800];                 // ||q||^2 per (b,t1)

// ---------------- helpers ----------------
__device__ __forceinline__ uint32_t smem_u32(const void* p) {
    uint32_t a;
    asm("{ .reg .u64 t; cvta.to.shared.u64 t, %1; cvt.u32.u64 %0, t; }" : "=r"(a) : "l"(p));
    return a;
}
__device__ __forceinline__ float tofloat(float v) { return v; }
__device__ __forceinline__ float tofloat(__nv_bfloat16 v) { return __bfloat162float(v); }

__device__ __forceinline__ void ldsm_x4(uint32_t& r0, uint32_t& r1, uint32_t& r2, uint32_t& r3,
                                        uint32_t addr) {
    asm volatile("ldmatrix.sync.aligned.m8n8.x4.shared.b16 {%0,%1,%2,%3}, [%4];"
                 : "=r"(r0), "=r"(r1), "=r"(r2), "=r"(r3) : "r"(addr));
}
__device__ __forceinline__ void ldsm_x2(uint32_t& r0, uint32_t& r1, uint32_t addr) {
    asm volatile("ldmatrix.sync.aligned.m8n8.x2.shared.b16 {%0,%1}, [%2];"
                 : "=r"(r0), "=r"(r1) : "r"(addr));
}
__device__ __forceinline__ void mma16816(float* c, uint32_t a0, uint32_t a1, uint32_t a2,
                                         uint32_t a3, uint32_t b0, uint32_t b1) {
    asm volatile("mma.sync.aligned.m16n8k16.row.col.f32.bf16.bf16.f32 "
                 "{%0,%1,%2,%3}, {%4,%5,%6,%7}, {%8,%9}, {%0,%1,%2,%3};"
                 : "+f"(c[0]), "+f"(c[1]), "+f"(c[2]), "+f"(c[3])
                 : "r"(a0), "r"(a1), "r"(a2), "r"(a3), "r"(b0), "r"(b1));
}

// smem footprint (shared between host launch + kernel)
__host__ __device__ constexpr size_t conv_smem(int KT, int CIN, int KC, int WM, int WN, int NT) {
    int PAD  = (KT == 3) ? 1 : 0;
    int BN   = 8 * NT * WN;
    int ROWS = BN + 2 * PAD;
    int CINP = CIN + 8;
    int KCP  = KC + 8;
    int BM   = 16 * WM;
    return (size_t)ROWS * CINP * 2 + (size_t)KT * BM * KCP * 2;
}

// ---------------- conv-as-GEMM via bf16 mma.sync, v2 ----------------
// Y[b,co,t] = sum_s sum_ci W[co,ci,s] * X[b,ci,t+s-PAD] + bias  (opt ReLU)
// X staged ONCE per block, t-major [t][ci] with padded stride CIN+8 (bank-safe
// for ldmatrix). W staged in CIN/KC chunks, layout [s][co][k] stride KC+8.
// Warp (wm,wn): co rows co0+wm*16..+15, NT n-tiles of 8 t at t0+wn*NT*8.
template<typename TIN, int KT, int CIN, int KC, int WM, int WN, int NT, bool RELU>
__global__ __launch_bounds__(32 * WM * WN)
void conv_mma_v2(const TIN* __restrict__ x, const float* __restrict__ w,
                 const float* __restrict__ bias, __nv_bfloat16* __restrict__ y,
                 int Cout, int T)
{
    constexpr int THREADS = 32 * WM * WN;
    constexpr int BM   = 16 * WM;
    constexpr int BN   = 8 * NT * WN;
    constexpr int PAD  = (KT == 3) ? 1 : 0;
    constexpr int ROWS = BN + 2 * PAD;
    constexpr int CINP = CIN + 8;
    constexpr int KCP  = KC + 8;
    constexpr int NCH  = CIN / KC;

    extern __shared__ __align__(16) char smem_raw[];
    __nv_bfloat16* xs = (__nv_bfloat16*)smem_raw;
    __nv_bfloat16* ws = xs + ROWS * CINP;

    const int b    = blockIdx.z;
    const int co0  = blockIdx.y * BM;
    const int t0   = blockIdx.x * BN;
    const int tid  = threadIdx.x;
    const int lane = tid & 31;
    const int warp = tid >> 5;
    const int wm   = warp % WM;
    const int wn   = warp / WM;

    float acc[NT][4];
    #pragma unroll
    for (int nt = 0; nt < NT; ++nt)
        #pragma unroll
        for (int i = 0; i < 4; ++i) acc[nt][i] = 0.f;

    const uint32_t xs_u = smem_u32(xs);
    const uint32_t ws_u = smem_u32(ws);

    // per-lane ldmatrix address components (canonical m16n8k16 frags, verified R6)
    const int a_row  = lane & 15;
    const int a_kh   = (lane >> 4) * 8;
    const int b_row  = (lane & 7) + ((lane >> 4) & 1) * 8;  // x4: 2 n-tiles
    const int b_kh   = ((lane >> 3) & 1) * 8;
    const int b_row2 = lane & 7;                            // x2 tail tile

    const TIN* xb = x + (size_t)b * CIN * T;

    // ---- stage X once: rows r -> t = t0+r-PAD, cols ci ----
    for (int idx = tid; idx < ROWS * CIN; idx += THREADS) {
        int ci = idx / ROWS;
        int r  = idx - ci * ROWS;
        int t  = t0 + r - PAD;
        float v = 0.f;
        if (t >= 0 && t < T) v = tofloat(xb[(size_t)ci * T + t]);
        xs[r * CINP + ci] = __float2bfloat16(v);
    }

    for (int cc = 0; cc < NCH; ++cc) {
        if (cc) __syncthreads();
        // ---- stage W chunk: [s][co][k], gmem (Cout, CIN, KT) ----
        for (int idx = tid; idx < BM * KC * KT; idx += THREADS) {
            int co  = idx / (KC * KT);
            int rem = idx - co * (KC * KT);
            int k   = rem / KT;
            int s   = rem - k * KT;
            float v = w[(size_t)(co0 + co) * (CIN * KT) + (size_t)(cc * KC + k) * KT + s];
            ws[(s * BM + co) * KCP + k] = __float2bfloat16(v);
        }
        __syncthreads();

        #pragma unroll
        for (int s = 0; s < KT; ++s) {
            #pragma unroll
            for (int kk = 0; kk < KC / 16; ++kk) {
                uint32_t a0, a1, a2, a3;
                uint32_t aaddr = ws_u +
                    (uint32_t)(((s * BM + wm * 16 + a_row) * KCP + kk * 16 + a_kh) * 2);
                ldsm_x4(a0, a1, a2, a3, aaddr);
                const int cibase = cc * KC + kk * 16;
                #pragma unroll
                for (int nt = 0; nt + 1 < NT; nt += 2) {
                    int n0 = wn * NT * 8 + nt * 8;
                    uint32_t baddr = xs_u +
                        (uint32_t)(((n0 + b_row + s) * CINP + cibase + b_kh) * 2);
                    uint32_t b0, b1, b2, b3;
                    ldsm_x4(b0, b1, b2, b3, baddr);
                    mma16816(acc[nt],     a0, a1, a2, a3, b0, b1);
                    mma16816(acc[nt + 1], a0, a1, a2, a3, b2, b3);
                }
                if (NT & 1) {
                    int nt = NT - 1;
                    int n0 = wn * NT * 8 + nt * 8;
                    uint32_t baddr = xs_u +
                        (uint32_t)(((n0 + b_row2 + s) * CINP + cibase + b_kh) * 2);
                    uint32_t b0, b1;
                    ldsm_x2(b0, b1, baddr);
                    mma16816(acc[nt], a0, a1, a2, a3, b0, b1);
                }
            }
        }
    }

    // ---- epilogue: c0,c1 -> (co g, t tg*2,+1); c2,c3 -> co g+8 ----
    const int g = lane >> 2, tg = lane & 3;
    const int coA = co0 + wm * 16 + g;
    const int coB = coA + 8;
    const float bA = bias[coA], bB = bias[coB];
    __nv_bfloat16* yb = y + (size_t)b * Cout * T;
    #pragma unroll
    for (int nt = 0; nt < NT; ++nt) {
        int t = t0 + wn * NT * 8 + nt * 8 + tg * 2;
        if (t < T) {
            float v0 = acc[nt][0] + bA, v1 = acc[nt][1] + bA;
            float v2 = acc[nt][2] + bB, v3 = acc[nt][3] + bB;
            if (RELU) {
                v0 = v0 > 0.f ? v0 : 0.f; v1 = v1 > 0.f ? v1 : 0.f;
                v2 = v2 > 0.f ? v2 : 0.f; v3 = v3 > 0.f ? v3 : 0.f;
            }
            __nv_bfloat162 p0, p1;
            p0.x = __float2bfloat16(v0); p0.y = __float2bfloat16(v1);
            p1.x = __float2bfloat16(v2); p1.y = __float2bfloat16(v3);
            *(__nv_bfloat162*)(yb + (size_t)coA * T + t) = p0;
            *(__nv_bfloat162*)(yb + (size_t)coB * T + t) = p1;
        }
    }
}

// ---------------- sum of squares over channels (bf16 input) ----------------
__global__ void sumsq_bf_kernel(const __nv_bfloat16* __restrict__ x, float* __restrict__ out,
                                int C, int T, int total)
{
    int idx = blockIdx.x * blockDim.x + threadIdx.x;
    if (idx >= total) return;
    int b = idx / T, t = idx % T;
    const __nv_bfloat16* p = x + (size_t)b * C * T + t;
    float s = 0.f;
    for (int c = 0; c < C; ++c) {
        float v = __bfloat162float(p[(size_t)c * T]);
        s = fmaf(v, v, s);
    }
    out[idx] = s;
}

// ---------------- logits = -5e-4 * (||q||^2 + ||k||^2 - 2 q.k) ----------------
__global__ __launch_bounds__(128)
void attn_logits_kernel(const __nv_bfloat16* __restrict__ q, const __nv_bfloat16* __restrict__ k,
                        const float* __restrict__ q2, const float* __restrict__ k2,
                        float* __restrict__ out)
{
    constexpr int C = 80;
    __shared__ float ks[40 * T2D];
    __shared__ float qs[32 * 81];
    __shared__ float k2s[T2D];

    const int b      = blockIdx.y;
    const int t1base = blockIdx.x * 32;
    const int tid    = threadIdx.x;
    const int t1l    = tid >> 3;
    const int t2g    = tid & 7;
    const int toff   = t2g * 25;

    float acc0[25], acc1[25];
    #pragma unroll
    for (int j = 0; j < 25; ++j) { acc0[j] = 0.f; acc1[j] = 0.f; }

    for (int idx = tid; idx < 32 * C; idx += 128) {
        int c = idx >> 5, r = idx & 31;
        qs[r * 81 + c] = __bfloat162float(q[((size_t)b * C + c) * T1D + t1base + r]);
    }
    for (int idx = tid; idx < T2D; idx += 128) k2s[idx] = k2[b * T2D + idx];
    float q2v0 = q2[b * T1D + t1base + t1l];
    float q2v1 = q2[b * T1D + t1base + t1l + 16];

    for (int cc = 0; cc < 2; ++cc) {
        for (int idx = tid; idx < 40 * T2D; idx += 128) {
            ks[idx] = __bfloat162float(
                k[((size_t)b * C + cc * 40 + (idx / T2D)) * T2D + (idx % T2D)]);
        }
        __syncthreads();
        for (int ci = 0; ci < 40; ++ci) {
            float qv0 = qs[t1l * 81 + cc * 40 + ci];
            float qv1 = qs[(t1l + 16) * 81 + cc * 40 + ci];
            const float* kr = &ks[ci * T2D + toff];
            #pragma unroll
            for (int j = 0; j < 25; ++j) {
                float kv = kr[j];
                acc0[j] = fmaf(qv0, kv, acc0[j]);
                acc1[j] = fmaf(qv1, kv, acc1[j]);
            }
        }
        __syncthreads();
    }

    const int t1a = t1base + t1l;
    float* o0 = out + ((size_t)b * T1D + t1a) * T2D + toff;
    float* o1 = out + ((size_t)b * T1D + t1a + 16) * T2D + toff;
    #pragma unroll
    for (int j = 0; j < 25; ++j) {
        float kk = k2s[toff + j];
        o0[j] = -0.0005f * (q2v0 + kk - 2.f * acc0[j]);
        o1[j] = -0.0005f * (q2v1 + kk - 2.f * acc1[j]);
    }
}

// ---------------- in-place log_softmax over t2 + log(prior + 1e-8) ----------------
__global__ __launch_bounds__(256)
void softmax_prior_kernel(float* __restrict__ out, const float* __restrict__ prior)
{
    int row  = blockIdx.x * 8 + (threadIdx.x >> 5);
    int lane = threadIdx.x & 31;
    float* p = out + (size_t)row * T2D;
    const float* pr = prior + (size_t)row * T2D;

    float v[7];
    float m = -1e30f;
    #pragma unroll
    for (int kk = 0; kk < 7; ++kk) {
        int i = lane + kk * 32;
        v[kk] = (i < T2D) ? p[i] : -1e30f;
        m = fmaxf(m, v[kk]);
    }
    #pragma unroll
    for (int off = 16; off; off >>= 1) m = fmaxf(m, __shfl_xor_sync(0xffffffff, m, off));
    float s = 0.f;
    #pragma unroll
    for (int kk = 0; kk < 7; ++kk) s += expf(v[kk] - m);
    #pragma unroll
    for (int off = 16; off; off >>= 1) s += __shfl_xor_sync(0xffffffff, s, off);
    float L = m + logf(s);
    #pragma unroll
    for (int kk = 0; kk < 7; ++kk) {
        int i = lane + kk * 32;
        if (i < T2D) p[i] = v[kk] - L + logf(pr[i] + 1e-8f);
    }
}

// ---------------- launch ----------------
extern "C" void kernel_launch(void* const* d_in, const int* in_sizes, int n_in,
                              void* d_out, int out_size)
{
    const float* queries = (const float*)d_in[0];   // (16,80,800)
    const float* keys    = (const float*)d_in[1];   // (16,256,200)
    const float* prior   = (const float*)d_in[2];   // (16,800,200)
    const float* kw1     = (const float*)d_in[3];   // (512,256,3)
    const float* kb1     = (const float*)d_in[4];
    const float* kw2     = (const float*)d_in[5];   // (80,512,1)
    const float* kb2     = (const float*)d_in[6];
    const float* qw1     = (const float*)d_in[7];   // (160,80,3)
    const float* qb1     = (const float*)d_in[8];
    const float* qw2     = (const float*)d_in[9];   // (80,160,1)
    const float* qb2     = (const float*)d_in[10];
    const float* qw3     = (const float*)d_in[11];  // (80,80,1)
    const float* qb3     = (const float*)d_in[12];
    float* out = (float*)d_out;

    __nv_bfloat16 *k1b, *kkb, *q1b, *qmb, *qqb;
    float *k2p, *q2p;
    cudaGetSymbolAddress((void**)&k1b, g_k1b);
    cudaGetSymbolAddress((void**)&kkb, g_kkb);
    cudaGetSymbolAddress((void**)&q1b, g_q1b);
    cudaGetSymbolAddress((void**)&qmb, g_qmb);
    cudaGetSymbolAddress((void**)&qqb, g_qqb);
    cudaGetSymbolAddress((void**)&k2p, g_k2);
    cudaGetSymbolAddress((void**)&q2p, g_q2);

    // smem sizes per instantiation
    constexpr size_t SM_KC1 = conv_smem(3, 256, 128, 4, 2, 13);  // key conv1: 163104
    constexpr size_t SM_K11 = conv_smem(1, 512, 128, 5, 1, 13);  // key 1x1:   129920
    constexpr size_t SM_QC1 = conv_smem(3,  80,  80, 2, 2, 13);  // q conv3:    53856
    constexpr size_t SM_Q12 = conv_smem(1, 160, 160, 5, 1, 13);  // q 1x1 a:    61824
    constexpr size_t SM_Q13 = conv_smem(1,  80,  80, 5, 1, 13);  // q 1x1 b:    32384

    cudaFuncSetAttribute((const void*)conv_mma_v2<float, 3, 256, 128, 4, 2, 13, true>,
                         cudaFuncAttributeMaxDynamicSharedMemorySize, (int)SM_KC1);
    cudaFuncSetAttribute((const void*)conv_mma_v2<__nv_bfloat16, 1, 512, 128, 5, 1, 13, false>,
                         cudaFuncAttributeMaxDynamicSharedMemorySize, (int)SM_K11);
    cudaFuncSetAttribute((const void*)conv_mma_v2<float, 3, 80, 80, 2, 2, 13, true>,
                         cudaFuncAttributeMaxDynamicSharedMemorySize, (int)SM_QC1);
    cudaFuncSetAttribute((const void*)conv_mma_v2<__nv_bfloat16, 1, 160, 160, 5, 1, 13, true>,
                         cudaFuncAttributeMaxDynamicSharedMemorySize, (int)SM_Q12);
    cudaFuncSetAttribute((const void*)conv_mma_v2<__nv_bfloat16, 1, 80, 80, 5, 1, 13, false>,
                         cudaFuncAttributeMaxDynamicSharedMemorySize, (int)SM_Q13);

    // key encoder: 256->512 k3 relu (BM=64, BN=208, 1 t-block); 512->80 1x1 (BN=104 x2)
    conv_mma_v2<float, 3, 256, 128, 4, 2, 13, true>
        <<<dim3(1, 8, NB), 256, SM_KC1>>>(keys, kw1, kb1, k1b, 512, T2D);
    conv_mma_v2<__nv_bfloat16, 1, 512, 128, 5, 1, 13, false>
        <<<dim3(2, 1, NB), 160, SM_K11>>>(k1b, kw2, kb2, kkb, 80, T2D);
    sumsq_bf_kernel<<<(NB * T2D + 255) / 256, 256>>>(kkb, k2p, 80, T2D, NB * T2D);

    // query encoder: 80->160 k3 relu (BM=32, BN=208 x4); 160->80 1x1 relu; 80->80 1x1
    conv_mma_v2<float, 3, 80, 80, 2, 2, 13, true>
        <<<dim3(4, 5, NB), 128, SM_QC1>>>(queries, qw1, qb1, q1b, 160, T1D);
    conv_mma_v2<__nv_bfloat16, 1, 160, 160, 5, 1, 13, true>
        <<<dim3(8, 1, NB), 160, SM_Q12>>>(q1b, qw2, qb2, qmb, 80, T1D);
    conv_mma_v2<__nv_bfloat16, 1, 80, 80, 5, 1, 13, false>
        <<<dim3(8, 1, NB), 160, SM_Q13>>>(qmb, qw3, qb3, qqb, 80, T1D);
    sumsq_bf_kernel<<<(NB * T1D + 255) / 256, 256>>>(qqb, q2p, 80, T1D, NB * T1D);

    // attention logits + log_softmax + prior
    attn_logits_kernel<<<dim3(25, NB), 128>>>(qqb, kkb, q2p, k2p, out);
    softmax_prior_kernel<<<NB * T1D / 8, 256>>>(out, prior);
}

// round 10
// speedup vs baseline: 4.3538x; 1.7021x over previous
#include <cuda_runtime.h>
#include <cuda_bf16.h>
#include <math.h>
#include <stdint.h>

// ---------------- problem constants ----------------
// B=16, Cmel=80, Ctxt=256, Catt=80, T1=800, T2=200
#define NB   16
#define T1D  800
#define T2D  200

// t-major image strides (bf16 elems). Rule: (stride/2) mod 32 in {4,12,20,28}
// so 8 ldmatrix rows hit 8 distinct bank groups.
#define XK_P 264   // keys   256+8
#define XQ_P 88    // queries 80+8
#define K1_P 536   // k1     512+24
#define Q1_P 168   // q1     160+8

// ---------------- scratch (no allocation allowed) ----------------
__device__ __nv_bfloat16 g_wimg[522752];           // repacked weights
__device__ __nv_bfloat16 g_xk [NB * T2D * XK_P];   // keys bf16 t-major
__device__ __nv_bfloat16 g_xq [NB * T1D * XQ_P];   // queries bf16 t-major
__device__ __nv_bfloat16 g_k1i[NB * T2D * K1_P];   // key conv1 out, t-major
__device__ __nv_bfloat16 g_q1i[NB * T1D * Q1_P];   // query conv1 out, t-major
__device__ __nv_bfloat16 g_kkb[NB * 80 * T2D];     // k (ci-major)
__device__ __nv_bfloat16 g_qqb[NB * 80 * T1D];     // q (ci-major)
__device__ float         g_k2 [NB * T2D];          // ||k||^2

// weight image section offsets (elems)
#define OFF_KC1 0
#define OFF_K11 417792
#define OFF_QC3 460032
#define OFF_Q12 502272
#define OFF_Q13 515712
#define W_TOTAL 522752

// ---------------- helpers ----------------
__device__ __forceinline__ uint32_t smem_u32(const void* p) {
    uint32_t a;
    asm("{ .reg .u64 t; cvta.to.shared.u64 t, %1; cvt.u32.u64 %0, t; }" : "=r"(a) : "l"(p));
    return a;
}
__device__ __forceinline__ void ldsm_x4(uint32_t& r0, uint32_t& r1, uint32_t& r2, uint32_t& r3,
                                        uint32_t addr) {
    asm volatile("ldmatrix.sync.aligned.m8n8.x4.shared.b16 {%0,%1,%2,%3}, [%4];"
                 : "=r"(r0), "=r"(r1), "=r"(r2), "=r"(r3) : "r"(addr));
}
__device__ __forceinline__ void ldsm_x2(uint32_t& r0, uint32_t& r1, uint32_t addr) {
    asm volatile("ldmatrix.sync.aligned.m8n8.x2.shared.b16 {%0,%1}, [%2];"
                 : "=r"(r0), "=r"(r1) : "r"(addr));
}
__device__ __forceinline__ void mma16816(float* c, uint32_t a0, uint32_t a1, uint32_t a2,
                                         uint32_t a3, uint32_t b0, uint32_t b1) {
    asm volatile("mma.sync.aligned.m16n8k16.row.col.f32.bf16.bf16.f32 "
                 "{%0,%1,%2,%3}, {%4,%5,%6,%7}, {%8,%9}, {%0,%1,%2,%3};"
                 : "+f"(c[0]), "+f"(c[1]), "+f"(c[2]), "+f"(c[3])
                 : "r"(a0), "r"(a1), "r"(a2), "r"(a3), "r"(b0), "r"(b1));
}

// ---------------- weight repack: fp32 -> bf16 smem-image layout ----------------
__global__ void prep_w_kernel(const float* __restrict__ kw1, const float* __restrict__ kw2,
                              const float* __restrict__ qw1, const float* __restrict__ qw2,
                              const float* __restrict__ qw3)
{
    int idx = blockIdx.x * blockDim.x + threadIdx.x;
    if (idx >= W_TOTAL) return;
    float v = 0.f;
    if (idx < OFF_K11) {                       // key conv1: [y4][cc2][s3][co128][k136], KC=128
        int l = idx;
        int k = l % 136; l /= 136;
        int co = l % 128; l /= 128;
        int s = l % 3; l /= 3;
        int cc = l % 2; int y = l / 2;
        if (k < 128) v = kw1[(size_t)(y * 128 + co) * 768 + (cc * 128 + k) * 3 + s];
    } else if (idx < OFF_QC3) {                // key 1x1: [cc2][co80][k264], KC=256
        int l = idx - OFF_K11;
        int k = l % 264; l /= 264;
        int co = l % 80; int cc = l / 80;
        if (k < 256) v = kw2[(size_t)co * 512 + cc * 256 + k];
    } else if (idx < OFF_Q12) {                // q conv3: [y2][s3][co80][k88], KC=80
        int l = idx - OFF_QC3;
        int k = l % 88; l /= 88;
        int co = l % 80; l /= 80;
        int s = l % 3; int y = l / 3;
        if (k < 80) v = qw1[(size_t)(y * 80 + co) * 240 + k * 3 + s];
    } else if (idx < OFF_Q13) {                // q 1x1 a: [co80][k168], KC=160
        int l = idx - OFF_Q12;
        int k = l % 168; int co = l / 168;
        if (k < 160) v = qw2[(size_t)co * 160 + k];
    } else {                                   // q 1x1 b: [co80][k88], KC=80
        int l = idx - OFF_Q13;
        int k = l % 88; int co = l / 88;
        if (k < 80) v = qw3[(size_t)co * 80 + k];
    }
    g_wimg[idx] = __float2bfloat16(v);
}

// ---------------- input transpose: fp32 [C][T] -> bf16 [T][CP] ----------------
__global__ void transpose_bf_kernel(const float* __restrict__ x, __nv_bfloat16* __restrict__ out,
                                    int C, int T, int CP)
{
    __shared__ float tile[32][33];
    int b = blockIdx.z;
    int t0 = blockIdx.x * 32, c0 = blockIdx.y * 32;
    int tx = threadIdx.x, ty = threadIdx.y;
    #pragma unroll
    for (int j = 0; j < 4; ++j) {
        int c = c0 + ty + j * 8, t = t0 + tx;
        tile[ty + j * 8][tx] = (c < C && t < T) ? x[((size_t)b * C + c) * T + t] : 0.f;
    }
    __syncthreads();
    #pragma unroll
    for (int j = 0; j < 4; ++j) {
        int t = t0 + ty + j * 8, c = c0 + tx;
        if (t < T && c < C)
            out[((size_t)b * T + t) * CP + c] = __float2bfloat16(tile[tx][ty + j * 8]);
    }
}

// ---------------- k=3 conv + ReLU, image in -> image out (t-major) ----------------
// X slab-copied once (uint4); W uint4-copied from g_wimg per chunk; ldmatrix+mma
// path identical to validated v2. Epilogue bounces through smem -> t-major image.
template<int CIN, int CINP, int KC, int WM, int NT, int OUTP>
__global__ __launch_bounds__(32 * WM)
void conv3_img_kernel(const __nv_bfloat16* __restrict__ xin, int wimg_off,
                      const float* __restrict__ bias, __nv_bfloat16* __restrict__ yimg, int T)
{
    constexpr int THREADS = 32 * WM;
    constexpr int BM = 16 * WM, BN = 8 * NT, ROWS = BN + 2;
    constexpr int KCP = KC + 8, NCH = CIN / KC;
    constexpr int XV = CINP / 8;             // uint4 per xs row
    constexpr int WCH = 3 * BM * KCP;        // elems per W chunk
    constexpr int BMP = BM + 8;

    extern __shared__ __align__(16) char sm[];
    __nv_bfloat16* xs = (__nv_bfloat16*)sm;
    __nv_bfloat16* ws = xs + ROWS * CINP;
    __nv_bfloat16* os = xs;                  // reuse after mainloop

    const int b = blockIdx.z, yb = blockIdx.y, t0 = blockIdx.x * BN;
    const int co0 = yb * BM;
    const int tid = threadIdx.x, lane = tid & 31, wm = tid >> 5;

    float acc[NT][4];
    #pragma unroll
    for (int nt = 0; nt < NT; ++nt)
        #pragma unroll
        for (int i = 0; i < 4; ++i) acc[nt][i] = 0.f;

    // ---- stage X once (slab copy, zero halo/tail) ----
    const uint4 z4 = make_uint4(0, 0, 0, 0);
    for (int idx = tid; idx < ROWS * XV; idx += THREADS) {
        int r = idx / XV, c = idx - r * XV;
        int t = t0 + r - 1;
        uint4 v = z4;
        if (t >= 0 && t < T) v = ((const uint4*)(xin + ((size_t)b * T + t) * CINP))[c];
        ((uint4*)xs)[idx] = v;
    }

    const uint32_t xs_u = smem_u32(xs), ws_u = smem_u32(ws);
    const int a_row = lane & 15, a_kh = (lane >> 4) * 8;
    const int b_row = (lane & 7) + ((lane >> 4) & 1) * 8;
    const int b_kh = ((lane >> 3) & 1) * 8;
    const int b_row2 = lane & 7;

    for (int cc = 0; cc < NCH; ++cc) {
        if (cc) __syncthreads();
        const uint4* wsrc = (const uint4*)(g_wimg + wimg_off + (size_t)(yb * NCH + cc) * WCH);
        for (int i = tid; i < WCH / 8; i += THREADS) ((uint4*)ws)[i] = wsrc[i];
        __syncthreads();

        #pragma unroll
        for (int s = 0; s < 3; ++s) {
            #pragma unroll
            for (int kk = 0; kk < KC / 16; ++kk) {
                uint32_t a0, a1, a2, a3;
                ldsm_x4(a0, a1, a2, a3,
                        ws_u + (uint32_t)(((s * BM + wm * 16 + a_row) * KCP + kk * 16 + a_kh) * 2));
                const int cb = cc * KC + kk * 16;
                #pragma unroll
                for (int nt = 0; nt + 1 < NT; nt += 2) {
                    uint32_t b0, b1, b2, b3;
                    ldsm_x4(b0, b1, b2, b3,
                            xs_u + (uint32_t)(((nt * 8 + b_row + s) * CINP + cb + b_kh) * 2));
                    mma16816(acc[nt],     a0, a1, a2, a3, b0, b1);
                    mma16816(acc[nt + 1], a0, a1, a2, a3, b2, b3);
                }
                {
                    uint32_t b0, b1;
                    ldsm_x2(b0, b1,
                            xs_u + (uint32_t)((((NT - 1) * 8 + b_row2 + s) * CINP + cb + b_kh) * 2));
                    mma16816(acc[NT - 1], a0, a1, a2, a3, b0, b1);
                }
            }
        }
    }

    __syncthreads();
    // ---- epilogue: relu(acc+bias) -> os[t][co], then slab-copy to yimg ----
    const int g = lane >> 2, tg = lane & 3;
    const int coA = wm * 16 + g, coB = coA + 8;
    const float bA = bias[co0 + coA], bB = bias[co0 + coB];
    #pragma unroll
    for (int nt = 0; nt < NT; ++nt) {
        int tl = nt * 8 + tg * 2;
        os[tl * BMP + coA]       = __float2bfloat16(fmaxf(acc[nt][0] + bA, 0.f));
        os[(tl + 1) * BMP + coA] = __float2bfloat16(fmaxf(acc[nt][1] + bA, 0.f));
        os[tl * BMP + coB]       = __float2bfloat16(fmaxf(acc[nt][2] + bB, 0.f));
        os[(tl + 1) * BMP + coB] = __float2bfloat16(fmaxf(acc[nt][3] + bB, 0.f));
    }
    __syncthreads();
    constexpr int OV = BM / 8;
    for (int idx = tid; idx < BN * OV; idx += THREADS) {
        int r = idx / OV, c = idx - r * OV;
        int t = t0 + r;
        if (t < T)
            ((uint4*)(yimg + ((size_t)b * T + t) * OUTP + co0))[c] =
                ((const uint4*)(os + r * BMP))[c];
    }
}

// ---------------- key 1x1 (512->80) + fused ||k||^2 ----------------
template<int CIN, int CINP, int KC, int WM, int NT>
__global__ __launch_bounds__(32 * WM)
void k11_kernel(const __nv_bfloat16* __restrict__ xin, int wimg_off,
                const float* __restrict__ bias, __nv_bfloat16* __restrict__ y,
                float* __restrict__ k2, int T)
{
    constexpr int THREADS = 32 * WM;
    constexpr int BM = 16 * WM, BN = 8 * NT;
    constexpr int KCP = KC + 8, NCH = CIN / KC;
    constexpr int XV = CINP / 8;
    constexpr int WCH = BM * KCP;

    extern __shared__ __align__(16) char sm[];
    __nv_bfloat16* xs = (__nv_bfloat16*)sm;
    __nv_bfloat16* ws = xs + BN * CINP;
    float* ss = (float*)(ws + WCH);

    const int b = blockIdx.z, t0 = blockIdx.x * BN;
    const int tid = threadIdx.x, lane = tid & 31, wm = tid >> 5;

    float acc[NT][4];
    #pragma unroll
    for (int nt = 0; nt < NT; ++nt)
        #pragma unroll
        for (int i = 0; i < 4; ++i) acc[nt][i] = 0.f;

    for (int i = tid; i < BN; i += THREADS) ss[i] = 0.f;

    const uint4 z4 = make_uint4(0, 0, 0, 0);
    for (int idx = tid; idx < BN * XV; idx += THREADS) {
        int r = idx / XV, c = idx - r * XV;
        int t = t0 + r;
        uint4 v = z4;
        if (t < T) v = ((const uint4*)(xin + ((size_t)b * T + t) * CINP))[c];
        ((uint4*)xs)[idx] = v;
    }

    const uint32_t xs_u = smem_u32(xs), ws_u = smem_u32(ws);
    const int a_row = lane & 15, a_kh = (lane >> 4) * 8;
    const int b_row = (lane & 7) + ((lane >> 4) & 1) * 8;
    const int b_kh = ((lane >> 3) & 1) * 8;
    const int b_row2 = lane & 7;

    for (int cc = 0; cc < NCH; ++cc) {
        if (cc) __syncthreads();
        const uint4* wsrc = (const uint4*)(g_wimg + wimg_off + (size_t)cc * WCH);
        for (int i = tid; i < WCH / 8; i += THREADS) ((uint4*)ws)[i] = wsrc[i];
        __syncthreads();

        #pragma unroll
        for (int kk = 0; kk < KC / 16; ++kk) {
            uint32_t a0, a1, a2, a3;
            ldsm_x4(a0, a1, a2, a3,
                    ws_u + (uint32_t)(((wm * 16 + a_row) * KCP + kk * 16 + a_kh) * 2));
            const int cb = cc * KC + kk * 16;
            #pragma unroll
            for (int nt = 0; nt + 1 < NT; nt += 2) {
                uint32_t b0, b1, b2, b3;
                ldsm_x4(b0, b1, b2, b3,
                        xs_u + (uint32_t)(((nt * 8 + b_row) * CINP + cb + b_kh) * 2));
                mma16816(acc[nt],     a0, a1, a2, a3, b0, b1);
                mma16816(acc[nt + 1], a0, a1, a2, a3, b2, b3);
            }
            {
                uint32_t b0, b1;
                ldsm_x2(b0, b1,
                        xs_u + (uint32_t)((((NT - 1) * 8 + b_row2) * CINP + cb + b_kh) * 2));
                mma16816(acc[NT - 1], a0, a1, a2, a3, b0, b1);
            }
        }
    }

    // epilogue: ci-major bf162 out + sumsq reduction
    const int g = lane >> 2, tg = lane & 3;
    const int coA = wm * 16 + g, coB = coA + 8;
    const float bA = bias[coA], bB = bias[coB];
    #pragma unroll
    for (int nt = 0; nt < NT; ++nt) {
        int tl = nt * 8 + tg * 2;
        int t = t0 + tl;
        float v0 = acc[nt][0] + bA, v1 = acc[nt][1] + bA;
        float v2 = acc[nt][2] + bB, v3 = acc[nt][3] + bB;
        if (t < T) {
            __nv_bfloat162 p0, p1;
            p0.x = __float2bfloat16(v0); p0.y = __float2bfloat16(v1);
            p1.x = __float2bfloat16(v2); p1.y = __float2bfloat16(v3);
            *(__nv_bfloat162*)(y + ((size_t)b * 80 + coA) * T + t) = p0;
            *(__nv_bfloat162*)(y + ((size_t)b * 80 + coB) * T + t) = p1;
        }
        float s0 = v0 * v0 + v2 * v2;
        float s1 = v1 * v1 + v3 * v3;
        #pragma unroll
        for (int off = 4; off < 32; off <<= 1) {
            s0 += __shfl_xor_sync(0xffffffff, s0, off);
            s1 += __shfl_xor_sync(0xffffffff, s1, off);
        }
        if (g == 0) {
            atomicAdd(&ss[tl], s0);
            atomicAdd(&ss[tl + 1], s1);
        }
    }
    __syncthreads();
    for (int i = tid; i < BN; i += THREADS) {
        int t = t0 + i;
        if (t < T) k2[b * T2D + t] = ss[i];
    }
}

// ---------------- fused query 1x1 (160->80 relu) -> 1x1 (80->80) ----------------
__global__ __launch_bounds__(160)
void qfused_kernel(const __nv_bfloat16* __restrict__ xin, const float* __restrict__ b2,
                   const float* __restrict__ b3, __nv_bfloat16* __restrict__ y, int T)
{
    constexpr int THREADS = 160, NT = 13, BN = 104;
    constexpr int CINP1 = Q1_P;       // 168
    constexpr int KCP2 = 168, KCP3 = 88, QMP = 88;

    extern __shared__ __align__(16) char sm[];
    __nv_bfloat16* xs  = (__nv_bfloat16*)sm;          // [104][168]
    __nv_bfloat16* w2s = xs + BN * CINP1;             // [80][168]
    __nv_bfloat16* qms = w2s + 80 * KCP2;             // [104][88]
    __nv_bfloat16* w3s = qms + BN * QMP;              // [80][88]

    const int b = blockIdx.z, t0 = blockIdx.x * BN;
    const int tid = threadIdx.x, lane = tid & 31, wm = tid >> 5;

    float acc[NT][4];
    #pragma unroll
    for (int nt = 0; nt < NT; ++nt)
        #pragma unroll
        for (int i = 0; i < 4; ++i) acc[nt][i] = 0.f;

    const uint4 z4 = make_uint4(0, 0, 0, 0);
    constexpr int XV = CINP1 / 8;
    for (int idx = tid; idx < BN * XV; idx += THREADS) {
        int r = idx / XV, c = idx - r * XV;
        int t = t0 + r;
        uint4 v = z4;
        if (t < T) v = ((const uint4*)(xin + ((size_t)b * T + t) * CINP1))[c];
        ((uint4*)xs)[idx] = v;
    }
    {
        const uint4* s2 = (const uint4*)(g_wimg + OFF_Q12);
        for (int i = tid; i < 80 * KCP2 / 8; i += THREADS) ((uint4*)w2s)[i] = s2[i];
        const uint4* s3 = (const uint4*)(g_wimg + OFF_Q13);
        for (int i = tid; i < 80 * KCP3 / 8; i += THREADS) ((uint4*)w3s)[i] = s3[i];
    }
    __syncthreads();

    const uint32_t xs_u = smem_u32(xs), w2_u = smem_u32(w2s);
    const uint32_t qm_u = smem_u32(qms), w3_u = smem_u32(w3s);
    const int a_row = lane & 15, a_kh = (lane >> 4) * 8;
    const int b_row = (lane & 7) + ((lane >> 4) & 1) * 8;
    const int b_kh = ((lane >> 3) & 1) * 8;
    const int b_row2 = lane & 7;
    const int g = lane >> 2, tg = lane & 3;
    const int coA = wm * 16 + g, coB = coA + 8;

    // ---- stage 1: q1 (160) -> qm (80), relu ----
    #pragma unroll
    for (int kk = 0; kk < 10; ++kk) {
        uint32_t a0, a1, a2, a3;
        ldsm_x4(a0, a1, a2, a3,
                w2_u + (uint32_t)(((wm * 16 + a_row) * KCP2 + kk * 16 + a_kh) * 2));
        #pragma unroll
        for (int nt = 0; nt + 1 < NT; nt += 2) {
            uint32_t b0, b1, b2, b3;
            ldsm_x4(b0, b1, b2, b3,
                    xs_u + (uint32_t)(((nt * 8 + b_row) * CINP1 + kk * 16 + b_kh) * 2));
            mma16816(acc[nt],     a0, a1, a2, a3, b0, b1);
            mma16816(acc[nt + 1], a0, a1, a2, a3, b2, b3);
        }
        {
            uint32_t b0, b1;
            ldsm_x2(b0, b1,
                    xs_u + (uint32_t)((((NT - 1) * 8 + b_row2) * CINP1 + kk * 16 + b_kh) * 2));
            mma16816(acc[NT - 1], a0, a1, a2, a3, b0, b1);
        }
    }
    {
        const float bA = b2[coA], bB = b2[coB];
        #pragma unroll
        for (int nt = 0; nt < NT; ++nt) {
            int tl = nt * 8 + tg * 2;
            qms[tl * QMP + coA]       = __float2bfloat16(fmaxf(acc[nt][0] + bA, 0.f));
            qms[(tl + 1) * QMP + coA] = __float2bfloat16(fmaxf(acc[nt][1] + bA, 0.f));
            qms[tl * QMP + coB]       = __float2bfloat16(fmaxf(acc[nt][2] + bB, 0.f));
            qms[(tl + 1) * QMP + coB] = __float2bfloat16(fmaxf(acc[nt][3] + bB, 0.f));
            #pragma unroll
            for (int i = 0; i < 4; ++i) acc[nt][i] = 0.f;
        }
    }
    __syncthreads();

    // ---- stage 2: qm (80) -> q (80) ----
    #pragma unroll
    for (int kk = 0; kk < 5; ++kk) {
        uint32_t a0, a1, a2, a3;
        ldsm_x4(a0, a1, a2, a3,
                w3_u + (uint32_t)(((wm * 16 + a_row) * KCP3 + kk * 16 + a_kh) * 2));
        #pragma unroll
        for (int nt = 0; nt + 1 < NT; nt += 2) {
            uint32_t b0, b1, b2, b3;
            ldsm_x4(b0, b1, b2, b3,
                    qm_u + (uint32_t)(((nt * 8 + b_row) * QMP + kk * 16 + b_kh) * 2));
            mma16816(acc[nt],     a0, a1, a2, a3, b0, b1);
            mma16816(acc[nt + 1], a0, a1, a2, a3, b2, b3);
        }
        {
            uint32_t b0, b1;
            ldsm_x2(b0, b1,
                    qm_u + (uint32_t)((((NT - 1) * 8 + b_row2) * QMP + kk * 16 + b_kh) * 2));
            mma16816(acc[NT - 1], a0, a1, a2, a3, b0, b1);
        }
    }
    {
        const float bA = b3[coA], bB = b3[coB];
        #pragma unroll
        for (int nt = 0; nt < NT; ++nt) {
            int t = t0 + nt * 8 + tg * 2;
            if (t < T) {
                __nv_bfloat162 p0, p1;
                p0.x = __float2bfloat16(acc[nt][0] + bA);
                p0.y = __float2bfloat16(acc[nt][1] + bA);
                p1.x = __float2bfloat16(acc[nt][2] + bB);
                p1.y = __float2bfloat16(acc[nt][3] + bB);
                *(__nv_bfloat162*)(y + ((size_t)b * 80 + coA) * T + t) = p0;
                *(__nv_bfloat162*)(y + ((size_t)b * 80 + coB) * T + t) = p1;
            }
        }
    }
}

// ---------------- fused logits + log_softmax + log(prior) ----------------
// logit' = -5e-4*(k2 - 2 qk)   (q2 term is constant over t2 -> cancels in log_softmax)
__global__ __launch_bounds__(128)
void attn_fused_kernel(const __nv_bfloat16* __restrict__ q, const __nv_bfloat16* __restrict__ k,
                       const float* __restrict__ k2, const float* __restrict__ prior,
                       float* __restrict__ out)
{
    constexpr int C = 80;
    __shared__ float ks[40 * T2D];
    __shared__ float qs[32 * 81];
    __shared__ float k2s[T2D];

    const int b      = blockIdx.y;
    const int t1base = blockIdx.x * 32;
    const int tid    = threadIdx.x;
    const int t1l    = tid >> 3;
    const int t2g    = tid & 7;
    const int toff   = t2g * 25;

    float acc0[25], acc1[25];
    #pragma unroll
    for (int j = 0; j < 25; ++j) { acc0[j] = 0.f; acc1[j] = 0.f; }

    for (int idx = tid; idx < 32 * C; idx += 128) {
        int c = idx >> 5, r = idx & 31;
        qs[r * 81 + c] = __bfloat162float(q[((size_t)b * C + c) * T1D + t1base + r]);
    }
    for (int idx = tid; idx < T2D; idx += 128) k2s[idx] = k2[b * T2D + idx];

    for (int cc = 0; cc < 2; ++cc) {
        for (int idx = tid; idx < 40 * T2D; idx += 128) {
            ks[idx] = __bfloat162float(
                k[((size_t)b * C + cc * 40 + (idx / T2D)) * T2D + (idx % T2D)]);
        }
        __syncthreads();
        for (int ci = 0; ci < 40; ++ci) {
            float qv0 = qs[t1l * 81 + cc * 40 + ci];
            float qv1 = qs[(t1l + 16) * 81 + cc * 40 + ci];
            const float* kr = &ks[ci * T2D + toff];
            #pragma unroll
            for (int j = 0; j < 25; ++j) {
                float kv = kr[j];
                acc0[j] = fmaf(qv0, kv, acc0[j]);
                acc1[j] = fmaf(qv1, kv, acc1[j]);
            }
        }
        __syncthreads();
    }

    // logits (q2 dropped: constant per row)
    #pragma unroll
    for (int j = 0; j < 25; ++j) {
        float kk = -0.0005f * k2s[toff + j];
        acc0[j] = fmaf(0.001f, acc0[j], kk);
        acc1[j] = fmaf(0.001f, acc1[j], kk);
    }

    // row reductions across the 8 threads (t2g) sharing a t1 row
    float m0 = -1e30f, m1 = -1e30f;
    #pragma unroll
    for (int j = 0; j < 25; ++j) { m0 = fmaxf(m0, acc0[j]); m1 = fmaxf(m1, acc1[j]); }
    #pragma unroll
    for (int off = 1; off < 8; off <<= 1) {
        m0 = fmaxf(m0, __shfl_xor_sync(0xffffffff, m0, off));
        m1 = fmaxf(m1, __shfl_xor_sync(0xffffffff, m1, off));
    }
    float s0 = 0.f, s1 = 0.f;
    #pragma unroll
    for (int j = 0; j < 25; ++j) { s0 += __expf(acc0[j] - m0); s1 += __expf(acc1[j] - m1); }
    #pragma unroll
    for (int off = 1; off < 8; off <<= 1) {
        s0 += __shfl_xor_sync(0xffffffff, s0, off);
        s1 += __shfl_xor_sync(0xffffffff, s1, off);
    }
    float L0 = m0 + __logf(s0);
    float L1 = m1 + __logf(s1);

    const int t1a = t1base + t1l;
    const float* pr0 = prior + ((size_t)b * T1D + t1a) * T2D + toff;
    const float* pr1 = pr0 + (size_t)16 * T2D;
    float* o0 = out + ((size_t)b * T1D + t1a) * T2D + toff;
    float* o1 = o0 + (size_t)16 * T2D;
    #pragma unroll
    for (int j = 0; j < 25; ++j) {
        o0[j] = acc0[j] - L0 + __logf(pr0[j] + 1e-8f);
        o1[j] = acc1[j] - L1 + __logf(pr1[j] + 1e-8f);
    }
}

// ---------------- launch ----------------
extern "C" void kernel_launch(void* const* d_in, const int* in_sizes, int n_in,
                              void* d_out, int out_size)
{
    const float* queries = (const float*)d_in[0];   // (16,80,800)
    const float* keys    = (const float*)d_in[1];   // (16,256,200)
    const float* prior   = (const float*)d_in[2];   // (16,800,200)
    const float* kw1     = (const float*)d_in[3];   // (512,256,3)
    const float* kb1     = (const float*)d_in[4];
    const float* kw2     = (const float*)d_in[5];   // (80,512,1)
    const float* kb2     = (const float*)d_in[6];
    const float* qw1     = (const float*)d_in[7];   // (160,80,3)
    const float* qb1     = (const float*)d_in[8];
    const float* qw2     = (const float*)d_in[9];   // (80,160,1)
    const float* qb2     = (const float*)d_in[10];
    const float* qw3     = (const float*)d_in[11];  // (80,80,1)
    const float* qb3     = (const float*)d_in[12];
    float* out = (float*)d_out;

    __nv_bfloat16 *xkp, *xqp, *k1ip, *q1ip, *kkp, *qqp;
    float* k2p;
    cudaGetSymbolAddress((void**)&xkp, g_xk);
    cudaGetSymbolAddress((void**)&xqp, g_xq);
    cudaGetSymbolAddress((void**)&k1ip, g_k1i);
    cudaGetSymbolAddress((void**)&q1ip, g_q1i);
    cudaGetSymbolAddress((void**)&kkp, g_kkb);
    cudaGetSymbolAddress((void**)&qqp, g_qqb);
    cudaGetSymbolAddress((void**)&k2p, g_k2);

    // dynamic smem sizes
    constexpr int SM_KC1 = (106 * XK_P + 3 * 128 * 136) * 2;           // 160,416
    constexpr int SM_QC3 = (106 * XQ_P + 3 * 80 * 88) * 2;             //  60,896
    constexpr int SM_K11 = (104 * K1_P + 80 * 264) * 2 + 104 * 4;      // 154,144
    constexpr int SM_QF  = (104 * Q1_P + 80 * 168 + 104 * 88 + 80 * 88) * 2;  // 94,208

    cudaFuncSetAttribute((const void*)conv3_img_kernel<256, XK_P, 128, 8, 13, K1_P>,
                         cudaFuncAttributeMaxDynamicSharedMemorySize, SM_KC1);
    cudaFuncSetAttribute((const void*)conv3_img_kernel<80, XQ_P, 80, 5, 13, Q1_P>,
                         cudaFuncAttributeMaxDynamicSharedMemorySize, SM_QC3);
    cudaFuncSetAttribute((const void*)k11_kernel<512, K1_P, 256, 5, 13>,
                         cudaFuncAttributeMaxDynamicSharedMemorySize, SM_K11);
    cudaFuncSetAttribute((const void*)qfused_kernel,
                         cudaFuncAttributeMaxDynamicSharedMemorySize, SM_QF);

    // prep: weight repack + input transposes
    prep_w_kernel<<<(W_TOTAL + 255) / 256, 256>>>(kw1, kw2, qw1, qw2, qw3);
    transpose_bf_kernel<<<dim3(7, 8, NB), dim3(32, 8)>>>(keys, xkp, 256, T2D, XK_P);
    transpose_bf_kernel<<<dim3(25, 3, NB), dim3(32, 8)>>>(queries, xqp, 80, T1D, XQ_P);

    // key encoder
    conv3_img_kernel<256, XK_P, 128, 8, 13, K1_P>
        <<<dim3(2, 4, NB), 256, SM_KC1>>>(xkp, OFF_KC1, kb1, k1ip, T2D);
    conv3_img_kernel<80, XQ_P, 80, 5, 13, Q1_P>
        <<<dim3(8, 2, NB), 160, SM_QC3>>>(xqp, OFF_QC3, qb1, q1ip, T1D);
    k11_kernel<512, K1_P, 256, 5, 13>
        <<<dim3(2, 1, NB), 160, SM_K11>>>(k1ip, OFF_K11, kb2, kkp, k2p, T2D);
    qfused_kernel<<<dim3(8, 1, NB), 160, SM_QF>>>(q1ip, qb2, qb3, qqp, T1D);

    // attention: logits + log_softmax + prior (fused)
    attn_fused_kernel<<<dim3(25, NB), 128>>>(qqp, kkp, k2p, prior, out);
}

// round 12
// speedup vs baseline: 6.1673x; 1.4165x over previous
#include <cuda_runtime.h>
#include <cuda_bf16.h>
#include <math.h>
#include <stdint.h>

// ---------------- problem constants ----------------
// B=16, Cmel=80, Ctxt=256, Catt=80, T1=800, T2=200
#define NB   16
#define T1D  800
#define T2D  200

// t-major image strides (bf16 elems). Rule: (stride*2 bytes /4) mod 32 in {4,12,20,28}
#define XK_P 264   // keys    256+8
#define XQ_P 88    // queries  80+8
#define K1_P 536   // k1      512+24
#define Q1_P 168   // q1      160+8
#define AT_P 88    // q/k attention images 80+8

// ---------------- scratch (no allocation allowed) ----------------
__device__ __nv_bfloat16 g_wimg[522752];           // repacked weights
__device__ __nv_bfloat16 g_xk [NB * T2D * XK_P];   // keys bf16 t-major
__device__ __nv_bfloat16 g_xq [NB * T1D * XQ_P];   // queries bf16 t-major
__device__ __nv_bfloat16 g_k1i[NB * T2D * K1_P];   // key conv1 out, t-major
__device__ __nv_bfloat16 g_q1i[NB * T1D * Q1_P];   // query conv1 out, t-major
__device__ __nv_bfloat16 g_kki[NB * T2D * AT_P];   // k, t-major
__device__ __nv_bfloat16 g_qqi[NB * T1D * AT_P];   // q, t-major
__device__ float         g_k2 [NB * T2D];          // ||k||^2

// weight image section offsets (elems)
#define OFF_KC1 0
#define OFF_K11 417792
#define OFF_QC3 460032
#define OFF_Q12 502272
#define OFF_Q13 515712
#define W_TOTAL 522752

// ---------------- helpers ----------------
__device__ __forceinline__ uint32_t smem_u32(const void* p) {
    uint32_t a;
    asm("{ .reg .u64 t; cvta.to.shared.u64 t, %1; cvt.u32.u64 %0, t; }" : "=r"(a) : "l"(p));
    return a;
}
__device__ __forceinline__ void ldsm_x4(uint32_t& r0, uint32_t& r1, uint32_t& r2, uint32_t& r3,
                                        uint32_t addr) {
    asm volatile("ldmatrix.sync.aligned.m8n8.x4.shared.b16 {%0,%1,%2,%3}, [%4];"
                 : "=r"(r0), "=r"(r1), "=r"(r2), "=r"(r3) : "r"(addr));
}
__device__ __forceinline__ void ldsm_x2(uint32_t& r0, uint32_t& r1, uint32_t addr) {
    asm volatile("ldmatrix.sync.aligned.m8n8.x2.shared.b16 {%0,%1}, [%2];"
                 : "=r"(r0), "=r"(r1) : "r"(addr));
}
__device__ __forceinline__ void mma16816(float* c, uint32_t a0, uint32_t a1, uint32_t a2,
                                         uint32_t a3, uint32_t b0, uint32_t b1) {
    asm volatile("mma.sync.aligned.m16n8k16.row.col.f32.bf16.bf16.f32 "
                 "{%0,%1,%2,%3}, {%4,%5,%6,%7}, {%8,%9}, {%0,%1,%2,%3};"
                 : "+f"(c[0]), "+f"(c[1]), "+f"(c[2]), "+f"(c[3])
                 : "r"(a0), "r"(a1), "r"(a2), "r"(a3), "r"(b0), "r"(b1));
}

// Batched 13-n-tile step: issue ALL B ldmatrix up front (MLP), then 13 mmas.
// STR: xs row stride (elems); row0: base row (includes tap shift / wn offset).
template<int STR>
__device__ __forceinline__ void mma_row_batch13(
    float (&acc)[13][4], uint32_t a0, uint32_t a1, uint32_t a2, uint32_t a3,
    uint32_t xs_u, int row0, int colbase, int b_row, int b_kh, int b_row2)
{
    uint32_t bf[6][4];
    uint32_t bt0, bt1;
    #pragma unroll
    for (int p = 0; p < 6; ++p)
        ldsm_x4(bf[p][0], bf[p][1], bf[p][2], bf[p][3],
                xs_u + (uint32_t)(((row0 + p * 16 + b_row) * STR + colbase + b_kh) * 2));
    ldsm_x2(bt0, bt1,
            xs_u + (uint32_t)(((row0 + 96 + b_row2) * STR + colbase + b_kh) * 2));
    #pragma unroll
    for (int p = 0; p < 6; ++p) {
        mma16816(acc[2 * p],     a0, a1, a2, a3, bf[p][0], bf[p][1]);
        mma16816(acc[2 * p + 1], a0, a1, a2, a3, bf[p][2], bf[p][3]);
    }
    mma16816(acc[12], a0, a1, a2, a3, bt0, bt1);
}

// ---------------- weight repack: fp32 -> bf16 smem-image layout ----------------
__global__ void prep_w_kernel(const float* __restrict__ kw1, const float* __restrict__ kw2,
                              const float* __restrict__ qw1, const float* __restrict__ qw2,
                              const float* __restrict__ qw3)
{
    int idx = blockIdx.x * blockDim.x + threadIdx.x;
    if (idx >= W_TOTAL) return;
    float v = 0.f;
    if (idx < OFF_K11) {                       // key conv1: [y4][cc2][s3][co128][k136]
        int l = idx;
        int k = l % 136; l /= 136;
        int co = l % 128; l /= 128;
        int s = l % 3; l /= 3;
        int cc = l % 2; int y = l / 2;
        if (k < 128) v = kw1[(size_t)(y * 128 + co) * 768 + (cc * 128 + k) * 3 + s];
    } else if (idx < OFF_QC3) {                // key 1x1: [cc2][co80][k264]
        int l = idx - OFF_K11;
        int k = l % 264; l /= 264;
        int co = l % 80; int cc = l / 80;
        if (k < 256) v = kw2[(size_t)co * 512 + cc * 256 + k];
    } else if (idx < OFF_Q12) {                // q conv3: [y2][s3][co80][k88]
        int l = idx - OFF_QC3;
        int k = l % 88; l /= 88;
        int co = l % 80; l /= 80;
        int s = l % 3; int y = l / 3;
        if (k < 80) v = qw1[(size_t)(y * 80 + co) * 240 + k * 3 + s];
    } else if (idx < OFF_Q13) {                // q 1x1 a: [co80][k168]
        int l = idx - OFF_Q12;
        int k = l % 168; int co = l / 168;
        if (k < 160) v = qw2[(size_t)co * 160 + k];
    } else {                                   // q 1x1 b: [co80][k88]
        int l = idx - OFF_Q13;
        int k = l % 88; int co = l / 88;
        if (k < 80) v = qw3[(size_t)co * 80 + k];
    }
    g_wimg[idx] = __float2bfloat16(v);
}

// ---------------- input transpose: fp32 [C][T] -> bf16 [T][CP] ----------------
__global__ void transpose_bf_kernel(const float* __restrict__ x, __nv_bfloat16* __restrict__ out,
                                    int C, int T, int CP)
{
    __shared__ float tile[32][33];
    int b = blockIdx.z;
    int t0 = blockIdx.x * 32, c0 = blockIdx.y * 32;
    int tx = threadIdx.x, ty = threadIdx.y;
    #pragma unroll
    for (int j = 0; j < 4; ++j) {
        int c = c0 + ty + j * 8, t = t0 + tx;
        tile[ty + j * 8][tx] = (c < C && t < T) ? x[((size_t)b * C + c) * T + t] : 0.f;
    }
    __syncthreads();
    #pragma unroll
    for (int j = 0; j < 4; ++j) {
        int t = t0 + ty + j * 8, c = c0 + tx;
        if (t < T && c < C)
            out[((size_t)b * T + t) * CP + c] = __float2bfloat16(tile[tx][ty + j * 8]);
    }
}

// ---------------- k=3 conv + ReLU, image in -> image out (t-major) ----------------
template<int CIN, int CINP, int KC, int WM, int OUTP>
__global__ __launch_bounds__(32 * WM)
void conv3_img_kernel(const __nv_bfloat16* __restrict__ xin, int wimg_off,
                      const float* __restrict__ bias, __nv_bfloat16* __restrict__ yimg, int T)
{
    constexpr int THREADS = 32 * WM;
    constexpr int BM = 16 * WM, BN = 104, ROWS = BN + 2;
    constexpr int KCP = KC + 8, NCH = CIN / KC;
    constexpr int XV = CINP / 8;
    constexpr int WCH = 3 * BM * KCP;
    constexpr int BMP = BM + 8;

    extern __shared__ __align__(16) char sm[];
    __nv_bfloat16* xs = (__nv_bfloat16*)sm;
    __nv_bfloat16* ws = xs + ROWS * CINP;
    __nv_bfloat16* os = xs;

    const int b = blockIdx.z, yb = blockIdx.y, t0 = blockIdx.x * BN;
    const int co0 = yb * BM;
    const int tid = threadIdx.x, lane = tid & 31, wm = tid >> 5;

    float acc[13][4];
    #pragma unroll
    for (int nt = 0; nt < 13; ++nt)
        #pragma unroll
        for (int i = 0; i < 4; ++i) acc[nt][i] = 0.f;

    const uint4 z4 = make_uint4(0, 0, 0, 0);
    for (int idx = tid; idx < ROWS * XV; idx += THREADS) {
        int r = idx / XV, c = idx - r * XV;
        int t = t0 + r - 1;
        uint4 v = z4;
        if (t >= 0 && t < T) v = ((const uint4*)(xin + ((size_t)b * T + t) * CINP))[c];
        ((uint4*)xs)[idx] = v;
    }

    const uint32_t xs_u = smem_u32(xs), ws_u = smem_u32(ws);
    const int a_row = lane & 15, a_kh = (lane >> 4) * 8;
    const int b_row = (lane & 7) + ((lane >> 4) & 1) * 8;
    const int b_kh = ((lane >> 3) & 1) * 8;
    const int b_row2 = lane & 7;

    for (int cc = 0; cc < NCH; ++cc) {
        if (cc) __syncthreads();
        const uint4* wsrc = (const uint4*)(g_wimg + wimg_off + (size_t)(yb * NCH + cc) * WCH);
        for (int i = tid; i < WCH / 8; i += THREADS) ((uint4*)ws)[i] = wsrc[i];
        __syncthreads();

        #pragma unroll
        for (int s = 0; s < 3; ++s) {
            #pragma unroll
            for (int kk = 0; kk < KC / 16; ++kk) {
                uint32_t a0, a1, a2, a3;
                ldsm_x4(a0, a1, a2, a3,
                        ws_u + (uint32_t)(((s * BM + wm * 16 + a_row) * KCP + kk * 16 + a_kh) * 2));
                mma_row_batch13<CINP>(acc, a0, a1, a2, a3, xs_u, s,
                                      cc * KC + kk * 16, b_row, b_kh, b_row2);
            }
        }
    }

    __syncthreads();
    const int g = lane >> 2, tg = lane & 3;
    const int coA = wm * 16 + g, coB = coA + 8;
    const float bA = bias[co0 + coA], bB = bias[co0 + coB];
    #pragma unroll
    for (int nt = 0; nt < 13; ++nt) {
        int tl = nt * 8 + tg * 2;
        os[tl * BMP + coA]       = __float2bfloat16(fmaxf(acc[nt][0] + bA, 0.f));
        os[(tl + 1) * BMP + coA] = __float2bfloat16(fmaxf(acc[nt][1] + bA, 0.f));
        os[tl * BMP + coB]       = __float2bfloat16(fmaxf(acc[nt][2] + bB, 0.f));
        os[(tl + 1) * BMP + coB] = __float2bfloat16(fmaxf(acc[nt][3] + bB, 0.f));
    }
    __syncthreads();
    constexpr int OV = BM / 8;
    for (int idx = tid; idx < BN * OV; idx += THREADS) {
        int r = idx / OV, c = idx - r * OV;
        int t = t0 + r;
        if (t < T)
            ((uint4*)(yimg + ((size_t)b * T + t) * OUTP + co0))[c] =
                ((const uint4*)(os + r * BMP))[c];
    }
}

// ---------------- key 1x1 (512->80) + fused ||k||^2, t-major image out ----------------
__global__ __launch_bounds__(160)
void k11_kernel(const __nv_bfloat16* __restrict__ xin,
                const float* __restrict__ bias, __nv_bfloat16* __restrict__ yimg,
                float* __restrict__ k2, int T)
{
    constexpr int THREADS = 160, BN = 104;
    constexpr int CINP = K1_P, KC = 256, KCP = KC + 8, NCH = 2;
    constexpr int XV = CINP / 8;
    constexpr int WCH = 80 * KCP;

    extern __shared__ __align__(16) char sm[];
    __nv_bfloat16* xs = (__nv_bfloat16*)sm;
    __nv_bfloat16* ws = xs + BN * CINP;
    float* ss = (float*)(ws + WCH);
    __nv_bfloat16* os = xs;   // reuse after mainloop (needs 104*88 <= BN*CINP)

    const int b = blockIdx.z, t0 = blockIdx.x * BN;
    const int tid = threadIdx.x, lane = tid & 31, wm = tid >> 5;

    float acc[13][4];
    #pragma unroll
    for (int nt = 0; nt < 13; ++nt)
        #pragma unroll
        for (int i = 0; i < 4; ++i) acc[nt][i] = 0.f;

    for (int i = tid; i < BN; i += THREADS) ss[i] = 0.f;

    const uint4 z4 = make_uint4(0, 0, 0, 0);
    for (int idx = tid; idx < BN * XV; idx += THREADS) {
        int r = idx / XV, c = idx - r * XV;
        int t = t0 + r;
        uint4 v = z4;
        if (t < T) v = ((const uint4*)(xin + ((size_t)b * T + t) * CINP))[c];
        ((uint4*)xs)[idx] = v;
    }

    const uint32_t xs_u = smem_u32(xs), ws_u = smem_u32(ws);
    const int a_row = lane & 15, a_kh = (lane >> 4) * 8;
    const int b_row = (lane & 7) + ((lane >> 4) & 1) * 8;
    const int b_kh = ((lane >> 3) & 1) * 8;
    const int b_row2 = lane & 7;

    for (int cc = 0; cc < NCH; ++cc) {
        if (cc) __syncthreads();
        const uint4* wsrc = (const uint4*)(g_wimg + OFF_K11 + (size_t)cc * WCH);
        for (int i = tid; i < WCH / 8; i += THREADS) ((uint4*)ws)[i] = wsrc[i];
        __syncthreads();

        #pragma unroll
        for (int kk = 0; kk < KC / 16; ++kk) {
            uint32_t a0, a1, a2, a3;
            ldsm_x4(a0, a1, a2, a3,
                    ws_u + (uint32_t)(((wm * 16 + a_row) * KCP + kk * 16 + a_kh) * 2));
            mma_row_batch13<CINP>(acc, a0, a1, a2, a3, xs_u, 0,
                                  cc * KC + kk * 16, b_row, b_kh, b_row2);
        }
    }

    __syncthreads();
    const int g = lane >> 2, tg = lane & 3;
    const int coA = wm * 16 + g, coB = coA + 8;
    const float bA = bias[coA], bB = bias[coB];
    #pragma unroll
    for (int nt = 0; nt < 13; ++nt) {
        int tl = nt * 8 + tg * 2;
        float v0 = acc[nt][0] + bA, v1 = acc[nt][1] + bA;
        float v2 = acc[nt][2] + bB, v3 = acc[nt][3] + bB;
        os[tl * AT_P + coA]       = __float2bfloat16(v0);
        os[(tl + 1) * AT_P + coA] = __float2bfloat16(v1);
        os[tl * AT_P + coB]       = __float2bfloat16(v2);
        os[(tl + 1) * AT_P + coB] = __float2bfloat16(v3);
        float s0 = v0 * v0 + v2 * v2;
        float s1 = v1 * v1 + v3 * v3;
        #pragma unroll
        for (int off = 4; off < 32; off <<= 1) {
            s0 += __shfl_xor_sync(0xffffffff, s0, off);
            s1 += __shfl_xor_sync(0xffffffff, s1, off);
        }
        if (g == 0) {
            atomicAdd(&ss[tl], s0);
            atomicAdd(&ss[tl + 1], s1);
        }
    }
    __syncthreads();
    constexpr int OV = AT_P / 8;   // 11
    for (int idx = tid; idx < BN * OV; idx += THREADS) {
        int r = idx / OV, c = idx - r * OV;
        int t = t0 + r;
        if (t < T)
            ((uint4*)(yimg + ((size_t)b * T + t) * AT_P))[c] =
                ((const uint4*)(os + r * AT_P))[c];
    }
    for (int i = tid; i < BN; i += THREADS) {
        int t = t0 + i;
        if (t < T) k2[b * T2D + t] = ss[i];
    }
}

// ---------------- fused query 1x1 (160->80 relu) -> 1x1 (80->80), t-major out ----------------
__global__ __launch_bounds__(160)
void qfused_kernel(const __nv_bfloat16* __restrict__ xin, const float* __restrict__ b2,
                   const float* __restrict__ b3, __nv_bfloat16* __restrict__ yimg, int T)
{
    constexpr int THREADS = 160, BN = 104;
    constexpr int CINP1 = Q1_P;   // 168
    constexpr int KCP2 = 168, KCP3 = 88, QMP = 88;

    extern __shared__ __align__(16) char sm[];
    __nv_bfloat16* xs  = (__nv_bfloat16*)sm;          // [104][168]
    __nv_bfloat16* w2s = xs + BN * CINP1;             // [80][168]
    __nv_bfloat16* qms = w2s + 80 * KCP2;             // [104][88]
    __nv_bfloat16* w3s = qms + BN * QMP;              // [80][88]
    __nv_bfloat16* os  = xs;                          // reuse for stage-2 out

    const int b = blockIdx.z, t0 = blockIdx.x * BN;
    const int tid = threadIdx.x, lane = tid & 31, wm = tid >> 5;

    float acc[13][4];
    #pragma unroll
    for (int nt = 0; nt < 13; ++nt)
        #pragma unroll
        for (int i = 0; i < 4; ++i) acc[nt][i] = 0.f;

    const uint4 z4 = make_uint4(0, 0, 0, 0);
    constexpr int XV = CINP1 / 8;
    for (int idx = tid; idx < BN * XV; idx += THREADS) {
        int r = idx / XV, c = idx - r * XV;
        int t = t0 + r;
        uint4 v = z4;
        if (t < T) v = ((const uint4*)(xin + ((size_t)b * T + t) * CINP1))[c];
        ((uint4*)xs)[idx] = v;
    }
    {
        const uint4* s2 = (const uint4*)(g_wimg + OFF_Q12);
        for (int i = tid; i < 80 * KCP2 / 8; i += THREADS) ((uint4*)w2s)[i] = s2[i];
        const uint4* s3 = (const uint4*)(g_wimg + OFF_Q13);
        for (int i = tid; i < 80 * KCP3 / 8; i += THREADS) ((uint4*)w3s)[i] = s3[i];
    }
    __syncthreads();

    const uint32_t xs_u = smem_u32(xs), w2_u = smem_u32(w2s);
    const uint32_t qm_u = smem_u32(qms), w3_u = smem_u32(w3s);
    const int a_row = lane & 15, a_kh = (lane >> 4) * 8;
    const int b_row = (lane & 7) + ((lane >> 4) & 1) * 8;
    const int b_kh = ((lane >> 3) & 1) * 8;
    const int b_row2 = lane & 7;
    const int g = lane >> 2, tg = lane & 3;
    const int coA = wm * 16 + g, coB = coA + 8;

    // stage 1: q1 (160) -> qm (80), relu
    #pragma unroll
    for (int kk = 0; kk < 10; ++kk) {
        uint32_t a0, a1, a2, a3;
        ldsm_x4(a0, a1, a2, a3,
                w2_u + (uint32_t)(((wm * 16 + a_row) * KCP2 + kk * 16 + a_kh) * 2));
        mma_row_batch13<CINP1>(acc, a0, a1, a2, a3, xs_u, 0, kk * 16, b_row, b_kh, b_row2);
    }
    {
        const float bA = b2[coA], bB = b2[coB];
        #pragma unroll
        for (int nt = 0; nt < 13; ++nt) {
            int tl = nt * 8 + tg * 2;
            qms[tl * QMP + coA]       = __float2bfloat16(fmaxf(acc[nt][0] + bA, 0.f));
            qms[(tl + 1) * QMP + coA] = __float2bfloat16(fmaxf(acc[nt][1] + bA, 0.f));
            qms[tl * QMP + coB]       = __float2bfloat16(fmaxf(acc[nt][2] + bB, 0.f));
            qms[(tl + 1) * QMP + coB] = __float2bfloat16(fmaxf(acc[nt][3] + bB, 0.f));
            #pragma unroll
            for (int i = 0; i < 4; ++i) acc[nt][i] = 0.f;
        }
    }
    __syncthreads();

    // stage 2: qm (80) -> q (80)
    #pragma unroll
    for (int kk = 0; kk < 5; ++kk) {
        uint32_t a0, a1, a2, a3;
        ldsm_x4(a0, a1, a2, a3,
                w3_u + (uint32_t)(((wm * 16 + a_row) * KCP3 + kk * 16 + a_kh) * 2));
        mma_row_batch13<QMP>(acc, a0, a1, a2, a3, qm_u, 0, kk * 16, b_row, b_kh, b_row2);
    }
    {
        const float bA = b3[coA], bB = b3[coB];
        #pragma unroll
        for (int nt = 0; nt < 13; ++nt) {
            int tl = nt * 8 + tg * 2;
            os[tl * AT_P + coA]       = __float2bfloat16(acc[nt][0] + bA);
            os[(tl + 1) * AT_P + coA] = __float2bfloat16(acc[nt][1] + bA);
            os[tl * AT_P + coB]       = __float2bfloat16(acc[nt][2] + bB);
            os[(tl + 1) * AT_P + coB] = __float2bfloat16(acc[nt][3] + bB);
        }
    }
    __syncthreads();
    constexpr int OV = AT_P / 8;
    for (int idx = tid; idx < BN * OV; idx += THREADS) {
        int r = idx / OV, c = idx - r * OV;
        int t = t0 + r;
        if (t < T)
            ((uint4*)(yimg + ((size_t)b * T + t) * AT_P))[c] =
                ((const uint4*)(os + r * AT_P))[c];
    }
}

// ---------------- attention: mma logits + fused log_softmax + log(prior) ----------------
// Block: 32 t1 x 200 t2; 4 warps: wm = t1 half (16 rows), wn = t2 half (104 cols).
// logit = 1e-3*qk - 5e-4*k2[t2]  (q2 constant per row -> cancels in log_softmax)
__global__ __launch_bounds__(128)
void attn_mma_kernel(const __nv_bfloat16* __restrict__ qimg,
                     const __nv_bfloat16* __restrict__ kimg,
                     const float* __restrict__ k2, const float* __restrict__ prior,
                     float* __restrict__ out)
{
    constexpr int KROWS = 208;
    __shared__ __nv_bfloat16 ks[KROWS * AT_P];
    __shared__ __nv_bfloat16 qs[32 * AT_P];
    __shared__ float k2s[T2D];
    __shared__ float redm[2][32], reds[2][32];

    const int b = blockIdx.y, t1base = blockIdx.x * 32;
    const int tid = threadIdx.x, lane = tid & 31, warp = tid >> 5;
    const int wm = warp & 1, wn = warp >> 1;

    constexpr int KV = AT_P / 8;   // 11 uint4 per row
    const uint4 z4 = make_uint4(0, 0, 0, 0);
    for (int idx = tid; idx < KROWS * KV; idx += 128) {
        int r = idx / KV, c = idx - r * KV;
        uint4 v = z4;
        if (r < T2D) v = ((const uint4*)(kimg + ((size_t)b * T2D + r) * AT_P))[c];
        ((uint4*)ks)[idx] = v;
    }
    for (int idx = tid; idx < 32 * KV; idx += 128) {
        int r = idx / KV, c = idx - r * KV;
        ((uint4*)qs)[idx] = ((const uint4*)(qimg + ((size_t)b * T1D + t1base + r) * AT_P))[c];
    }
    for (int i = tid; i < T2D; i += 128) k2s[i] = k2[b * T2D + i];
    __syncthreads();

    float acc[13][4];
    #pragma unroll
    for (int nt = 0; nt < 13; ++nt)
        #pragma unroll
        for (int i = 0; i < 4; ++i) acc[nt][i] = 0.f;

    const uint32_t qs_u = smem_u32(qs), ks_u = smem_u32(ks);
    const int a_row = lane & 15, a_kh = (lane >> 4) * 8;
    const int b_row = (lane & 7) + ((lane >> 4) & 1) * 8;
    const int b_kh = ((lane >> 3) & 1) * 8;
    const int b_row2 = lane & 7;

    #pragma unroll
    for (int kk = 0; kk < 5; ++kk) {
        uint32_t a0, a1, a2, a3;
        ldsm_x4(a0, a1, a2, a3,
                qs_u + (uint32_t)(((wm * 16 + a_row) * AT_P + kk * 16 + a_kh) * 2));
        mma_row_batch13<AT_P>(acc, a0, a1, a2, a3, ks_u, wn * 104, kk * 16,
                              b_row, b_kh, b_row2);
    }

    // logits + mask (pair-valid: t2l even, so t2l<200 => t2l+1<200)
    const int g = lane >> 2, tg = lane & 3;
    #pragma unroll
    for (int nt = 0; nt < 13; ++nt) {
        int t2l = wn * 104 + nt * 8 + tg * 2;
        if (t2l < T2D) {
            float c0 = -0.0005f * k2s[t2l];
            float c1 = -0.0005f * k2s[t2l + 1];
            acc[nt][0] = fmaf(0.001f, acc[nt][0], c0);
            acc[nt][1] = fmaf(0.001f, acc[nt][1], c1);
            acc[nt][2] = fmaf(0.001f, acc[nt][2], c0);
            acc[nt][3] = fmaf(0.001f, acc[nt][3], c1);
        } else {
            acc[nt][0] = -1e30f; acc[nt][1] = -1e30f;
            acc[nt][2] = -1e30f; acc[nt][3] = -1e30f;
        }
    }

    // row max (this warp's t2-half)
    float m0 = -1e30f, m1 = -1e30f;
    #pragma unroll
    for (int nt = 0; nt < 13; ++nt) {
        m0 = fmaxf(m0, fmaxf(acc[nt][0], acc[nt][1]));
        m1 = fmaxf(m1, fmaxf(acc[nt][2], acc[nt][3]));
    }
    #pragma unroll
    for (int off = 1; off < 4; off <<= 1) {
        m0 = fmaxf(m0, __shfl_xor_sync(0xffffffff, m0, off));
        m1 = fmaxf(m1, __shfl_xor_sync(0xffffffff, m1, off));
    }
    if (tg == 0) {
        redm[wn][wm * 16 + g] = m0;
        redm[wn][wm * 16 + g + 8] = m1;
    }
    __syncthreads();
    const float M0 = fmaxf(redm[0][wm * 16 + g], redm[1][wm * 16 + g]);
    const float M1 = fmaxf(redm[0][wm * 16 + g + 8], redm[1][wm * 16 + g + 8]);

    // row exp-sum
    float s0 = 0.f, s1 = 0.f;
    #pragma unroll
    for (int nt = 0; nt < 13; ++nt) {
        s0 += __expf(acc[nt][0] - M0) + __expf(acc[nt][1] - M0);
        s1 += __expf(acc[nt][2] - M1) + __expf(acc[nt][3] - M1);
    }
    #pragma unroll
    for (int off = 1; off < 4; off <<= 1) {
        s0 += __shfl_xor_sync(0xffffffff, s0, off);
        s1 += __shfl_xor_sync(0xffffffff, s1, off);
    }
    if (tg == 0) {
        reds[wn][wm * 16 + g] = s0;
        reds[wn][wm * 16 + g + 8] = s1;
    }
    __syncthreads();
    const float L0 = M0 + __logf(reds[0][wm * 16 + g] + reds[1][wm * 16 + g]);
    const float L1 = M1 + __logf(reds[0][wm * 16 + g + 8] + reds[1][wm * 16 + g + 8]);

    // output: logit - L + log(prior + 1e-8)
    const int row0 = t1base + wm * 16 + g;
    const int row1 = row0 + 8;
    #pragma unroll
    for (int nt = 0; nt < 13; ++nt) {
        int t2l = wn * 104 + nt * 8 + tg * 2;
        if (t2l < T2D) {
            size_t o0 = ((size_t)b * T1D + row0) * T2D + t2l;
            size_t o1 = ((size_t)b * T1D + row1) * T2D + t2l;
            float2 pr0 = *(const float2*)(prior + o0);
            float2 pr1 = *(const float2*)(prior + o1);
            float2 r0, r1;
            r0.x = acc[nt][0] - L0 + __logf(pr0.x + 1e-8f);
            r0.y = acc[nt][1] - L0 + __logf(pr0.y + 1e-8f);
            r1.x = acc[nt][2] - L1 + __logf(pr1.x + 1e-8f);
            r1.y = acc[nt][3] - L1 + __logf(pr1.y + 1e-8f);
            *(float2*)(out + o0) = r0;
            *(float2*)(out + o1) = r1;
        }
    }
}

// ---------------- launch ----------------
extern "C" void kernel_launch(void* const* d_in, const int* in_sizes, int n_in,
                              void* d_out, int out_size)
{
    const float* queries = (const float*)d_in[0];   // (16,80,800)
    const float* keys    = (const float*)d_in[1];   // (16,256,200)
    const float* prior   = (const float*)d_in[2];   // (16,800,200)
    const float* kw1     = (const float*)d_in[3];   // (512,256,3)
    const float* kb1     = (const float*)d_in[4];
    const float* kw2     = (const float*)d_in[5];   // (80,512,1)
    const float* kb2     = (const float*)d_in[6];
    const float* qw1     = (const float*)d_in[7];   // (160,80,3)
    const float* qb1     = (const float*)d_in[8];
    const float* qw2     = (const float*)d_in[9];   // (80,160,1)
    const float* qb2     = (const float*)d_in[10];
    const float* qw3     = (const float*)d_in[11];  // (80,80,1)
    const float* qb3     = (const float*)d_in[12];
    float* out = (float*)d_out;

    __nv_bfloat16 *xkp, *xqp, *k1ip, *q1ip, *kkip, *qqip;
    float* k2p;
    cudaGetSymbolAddress((void**)&xkp, g_xk);
    cudaGetSymbolAddress((void**)&xqp, g_xq);
    cudaGetSymbolAddress((void**)&k1ip, g_k1i);
    cudaGetSymbolAddress((void**)&q1ip, g_q1i);
    cudaGetSymbolAddress((void**)&kkip, g_kki);
    cudaGetSymbolAddress((void**)&qqip, g_qqi);
    cudaGetSymbolAddress((void**)&k2p, g_k2);

    constexpr int SM_KC1 = (106 * XK_P + 3 * 128 * 136) * 2;                  // 160,416
    constexpr int SM_QC3 = (106 * XQ_P + 3 * 80 * 88) * 2;                    //  60,896
    constexpr int SM_K11 = (104 * K1_P + 80 * 264) * 2 + 104 * 4;             // 154,144
    constexpr int SM_QF  = (104 * Q1_P + 80 * 168 + 104 * 88 + 80 * 88) * 2;  //  94,208

    cudaFuncSetAttribute((const void*)conv3_img_kernel<256, XK_P, 128, 8, K1_P>,
                         cudaFuncAttributeMaxDynamicSharedMemorySize, SM_KC1);
    cudaFuncSetAttribute((const void*)conv3_img_kernel<80, XQ_P, 80, 5, Q1_P>,
                         cudaFuncAttributeMaxDynamicSharedMemorySize, SM_QC3);
    cudaFuncSetAttribute((const void*)k11_kernel,
                         cudaFuncAttributeMaxDynamicSharedMemorySize, SM_K11);
    cudaFuncSetAttribute((const void*)qfused_kernel,
                         cudaFuncAttributeMaxDynamicSharedMemorySize, SM_QF);

    // prep: weight repack + input transposes
    prep_w_kernel<<<(W_TOTAL + 255) / 256, 256>>>(kw1, kw2, qw1, qw2, qw3);
    transpose_bf_kernel<<<dim3(7, 8, NB), dim3(32, 8)>>>(keys, xkp, 256, T2D, XK_P);
    transpose_bf_kernel<<<dim3(25, 3, NB), dim3(32, 8)>>>(queries, xqp, 80, T1D, XQ_P);

    // encoders
    conv3_img_kernel<256, XK_P, 128, 8, K1_P>
        <<<dim3(2, 4, NB), 256, SM_KC1>>>(xkp, OFF_KC1, kb1, k1ip, T2D);
    conv3_img_kernel<80, XQ_P, 80, 5, Q1_P>
        <<<dim3(8, 2, NB), 160, SM_QC3>>>(xqp, OFF_QC3, qb1, q1ip, T1D);
    k11_kernel<<<dim3(2, 1, NB), 160, SM_K11>>>(k1ip, kb2, kkip, k2p, T2D);
    qfused_kernel<<<dim3(8, 1, NB), 160, SM_QF>>>(q1ip, qb2, qb3, qqip, T1D);

    // attention (fully fused)
    attn_mma_kernel<<<dim3(25, NB), 128>>>(qqip, kkip, k2p, prior, out);
}